// round 9
// baseline (speedup 1.0000x reference)
// v9: pass-major mma ordering (break accumulator RAW chains) + 64-key chunks
// for 96KB smem -> 2 CTA/SM in attention. Epilogues/fills from passing v8.
#include <cuda_runtime.h>
#include <cuda_bf16.h>
#include <cstdint>

#define Bc   4
#define Nseq 2048
#define Cdim 768
#define Hh   12
#define Dd   64

using u64 = unsigned long long;
using u32 = unsigned int;

#define QS_CONST 92.33248261972106f    // 64 * log2(e)
#define MC_CONST -1442695.040888963f   // -1e6 * log2(e)

__device__ __forceinline__ float ex2(float x) {
    float y; asm("ex2.approx.f32 %0,%1;" : "=f"(y) : "f"(x)); return y;
}
__device__ __forceinline__ u32 smem_u32(const void* p) {
    u32 a; asm("{ .reg .u64 t; cvta.to.shared.u64 t, %1; cvt.u32.u64 %0, t; }" : "=r"(a) : "l"(p));
    return a;
}
__device__ __forceinline__ void ldm4(u32& r0, u32& r1, u32& r2, u32& r3, u32 addr) {
    asm volatile("ldmatrix.sync.aligned.m8n8.x4.shared.b16 {%0,%1,%2,%3},[%4];"
        : "=r"(r0), "=r"(r1), "=r"(r2), "=r"(r3) : "r"(addr));
}
__device__ __forceinline__ void mma16816(float* c, const u32* a, u32 b0, u32 b1) {
    asm volatile("mma.sync.aligned.m16n8k16.row.col.f32.bf16.bf16.f32 "
        "{%0,%1,%2,%3},{%4,%5,%6,%7},{%8,%9},{%0,%1,%2,%3};"
        : "+f"(c[0]), "+f"(c[1]), "+f"(c[2]), "+f"(c[3])
        : "r"(a[0]), "r"(a[1]), "r"(a[2]), "r"(a[3]), "r"(b0), "r"(b1));
}
__device__ __forceinline__ u32 pkbf(float lo, float hi) {
    u32 r; asm("cvt.rn.bf16x2.f32 %0,%1,%2;" : "=r"(r) : "f"(hi), "f"(lo)); return r;
}
__device__ __forceinline__ void split2(float x, float y, u32& hi, u32& lo) {
    hi = pkbf(x, y);
    float hx = __int_as_float(hi << 16);
    float hy = __int_as_float(hi & 0xFFFF0000u);
    lo = pkbf(x - hx, y - hy);
}
__device__ __forceinline__ float exp2p(float x) {
    x = fmaxf(x, -126.0f);
    float t = x + 12582912.0f;
    int  k  = __float_as_int(t) - 0x4B400000;
    float xf = x - (t - 12582912.0f);
    float p = 0.0096180f;
    p = p * xf + 0.0555041f;
    p = p * xf + 0.2402265f;
    p = p * xf + 0.6931472f;
    p = p * xf + 1.0f;
    return p * __int_as_float((k + 127) << 23);
}
__device__ __forceinline__ void cpa16(u32 dst, const void* src) {
    asm volatile("cp.async.cg.shared.global [%0], [%1], 16;" :: "r"(dst), "l"(src) : "memory");
}
#define CP_COMMIT() asm volatile("cp.async.commit_group;" ::: "memory")
#define CP_WAIT(n)  asm volatile("cp.async.wait_group %0;" :: "n"(n) : "memory")

// Scratch: bf16 hi/lo QKV (Q pre-scaled; V pre-transposed) + fp32 attn out
__device__ __nv_bfloat16 g_qhi[(size_t)48 * 2048 * 64];
__device__ __nv_bfloat16 g_qlo[(size_t)48 * 2048 * 64];
__device__ __nv_bfloat16 g_khi[(size_t)48 * 2048 * 64];
__device__ __nv_bfloat16 g_klo[(size_t)48 * 2048 * 64];
__device__ __nv_bfloat16 g_vthi[(size_t)48 * 64 * 2048];   // [bh][d][n]
__device__ __nv_bfloat16 g_vtlo[(size_t)48 * 64 * 2048];
__device__ float g_ao[(size_t)Bc * Nseq * Cdim];           // [B][N][C]

// ===========================================================================
// HMMA split-bf16 GEMM NT. v8 structure; mma loop reordered pass-major so
// each acc register is revisited every 16 mmas instead of back-to-back.
// ===========================================================================
#define TILE_B 16384
#define STG_B  (4 * TILE_B)
#define GEMM_SMEM (2 * STG_B)

__device__ __forceinline__ void fill_pair(const float* __restrict__ src, char* hi,
                                          char* lo, int kbase, int t) {
#pragma unroll
    for (int it = 0; it < 8; ++it) {
        int f4  = t + it * 256;
        int row = f4 >> 4;
        int c4  = (f4 & 15) << 2;
        float4 v = *(const float4*)(src + (size_t)row * 768 + kbase + c4);
        u32 h01, l01, h23, l23;
        split2(v.x, v.y, h01, l01);
        split2(v.z, v.w, h23, l23);
        u32 off = (u32)(row * 128 + c4 * 2);
        u32 sw  = off ^ ((off >> 3) & 0x70);
        uint2 uh; uh.x = h01; uh.y = h23;
        uint2 ul; ul.x = l01; ul.y = l23;
        *(uint2*)(hi + sw) = uh;
        *(uint2*)(lo + sw) = ul;
    }
}

template<int MODE>
__global__ void __launch_bounds__(256) gemm_mma(const float* __restrict__ A_,
                                                const float* __restrict__ Bw,
                                                const float* __restrict__ bias,
                                                float* __restrict__ C, int Nn) {
    extern __shared__ __align__(1024) char smem[];
    const u32 sb   = smem_u32(smem);
    const int t    = threadIdx.x, lane = t & 31, wid = t >> 5;
    const int i0   = blockIdx.y * 128, j0 = blockIdx.x * 128;
    const float* __restrict__ Arow = ((MODE == 2) ? g_ao : A_) + (size_t)i0 * 768;
    const float* __restrict__ Brow = Bw + (size_t)j0 * 768;

    const int m0  = (wid >> 2) * 64;
    const int n0  = (wid & 3) * 32;
    const int lr  = lane & 15;
    const int chi = lane >> 4;
    const u32 xorv = (u32)((lane & 7) << 4);

    float acc[4][4][4];
#pragma unroll
    for (int i = 0; i < 4; i++)
#pragma unroll
        for (int j = 0; j < 4; j++)
#pragma unroll
            for (int k = 0; k < 4; k++) acc[i][j][k] = 0.f;

    fill_pair(Arow, smem + 0,          smem + TILE_B,     0, t);
    fill_pair(Brow, smem + 2 * TILE_B, smem + 3 * TILE_B, 0, t);
    __syncthreads();

    for (int kc = 0; kc < 12; ++kc) {
        const int st = kc & 1;
        if (kc + 1 < 12) {
            char* nb = smem + (st ^ 1) * STG_B;
            fill_pair(Arow, nb,              nb + TILE_B,     (kc + 1) * 64, t);
            fill_pair(Brow, nb + 2 * TILE_B, nb + 3 * TILE_B, (kc + 1) * 64, t);
        }
        __syncthreads();

        const u32 base = sb + st * STG_B;
#pragma unroll
        for (int s = 0; s < 4; ++s) {
            const u32 colterm = ((u32)((2 * s + chi) << 4)) ^ xorv;
            u32 ah[4][4], al[4][4];
#pragma unroll
            for (int i = 0; i < 4; i++) {
                u32 ra = base + (u32)((m0 + i * 16 + lr) * 128) + colterm;
                ldm4(ah[i][0], ah[i][1], ah[i][2], ah[i][3], ra);
                ldm4(al[i][0], al[i][1], al[i][2], al[i][3], ra + TILE_B);
            }
            u32 bh[8], bl[8];
#pragma unroll
            for (int j = 0; j < 2; j++) {
                u32 rb = base + 2 * TILE_B + (u32)((n0 + j * 16 + lr) * 128) + colterm;
                ldm4(bh[j * 4 + 0], bh[j * 4 + 1], bh[j * 4 + 2], bh[j * 4 + 3], rb);
                ldm4(bl[j * 4 + 0], bl[j * 4 + 1], bl[j * 4 + 2], bl[j * 4 + 3], rb + TILE_B);
            }
            // pass-major: each acc revisited every 16 mmas
#pragma unroll
            for (int i = 0; i < 4; i++)
#pragma unroll
                for (int jj = 0; jj < 4; jj++) {
                    int j4 = (jj >> 1) * 4 + (jj & 1);
                    mma16816(acc[i][jj], ah[i], bh[j4], bh[j4 + 2]);
                }
#pragma unroll
            for (int i = 0; i < 4; i++)
#pragma unroll
                for (int jj = 0; jj < 4; jj++) {
                    int j4 = (jj >> 1) * 4 + (jj & 1);
                    mma16816(acc[i][jj], ah[i], bl[j4], bl[j4 + 2]);
                }
#pragma unroll
            for (int i = 0; i < 4; i++)
#pragma unroll
                for (int jj = 0; jj < 4; jj++) {
                    int j4 = (jj >> 1) * 4 + (jj & 1);
                    mma16816(acc[i][jj], al[i], bh[j4], bh[j4 + 2]);
                }
        }
        __syncthreads();
    }

#pragma unroll
    for (int i = 0; i < 4; i++) {
        int r0 = m0 + i * 16 + (lane >> 2);
#pragma unroll
        for (int jj = 0; jj < 4; jj++) {
            int col = n0 + jj * 8 + 2 * (lane & 3);
#pragma unroll
            for (int half = 0; half < 2; half++) {
                int gi = i0 + r0 + half * 8;
                int gj = j0 + col;
                float2 v;
                v.x = acc[i][jj][half * 2 + 0];
                v.y = acc[i][jj][half * 2 + 1];
                if (MODE == 1) {
                    int b = gi >> 11, n = gi & 2047;
                    int three = gj / 768, rem = gj - three * 768;
                    int hh = rem >> 6, d = rem & 63;
                    int bhI = b * 12 + hh;
                    if (three < 2) {
                        float sc = (three == 0) ? QS_CONST : 1.0f;
                        u32 hi, lo;
                        split2(v.x * sc, v.y * sc, hi, lo);
                        size_t idx = ((size_t)bhI * 2048 + n) * 64 + d;
                        __nv_bfloat16* ph = (three == 0) ? g_qhi : g_khi;
                        __nv_bfloat16* pl = (three == 0) ? g_qlo : g_klo;
                        *(u32*)(ph + idx) = hi;
                        *(u32*)(pl + idx) = lo;
                    } else {
                        size_t b0 = ((size_t)bhI * 64 + d) * 2048 + n;
                        __nv_bfloat16 hx = __float2bfloat16(v.x);
                        g_vthi[b0] = hx;
                        g_vtlo[b0] = __float2bfloat16(v.x - __bfloat162float(hx));
                        __nv_bfloat16 hy = __float2bfloat16(v.y);
                        g_vthi[b0 + 2048] = hy;
                        g_vtlo[b0 + 2048] = __float2bfloat16(v.y - __bfloat162float(hy));
                    }
                } else {
                    v.x += bias[gj];
                    v.y += bias[gj + 1];
                    *(float2*)(C + (size_t)gi * Nn + gj) = v;
                }
            }
        }
    }
}

// ===========================================================================
// HMMA flash attention, 64-key chunks, 96KB smem -> 2 CTA/SM, pass-major mmas.
// smem: Q hi/lo 32KB + 2 stages x (Khi 8K, Klo 8K, Vthi 8K, Vtlo 8K) = 96KB.
// ===========================================================================
#define AQHI 0
#define AQLO 16384
#define STAGE0 32768
#define STG_SZ 32768
#define SKHI 0
#define SKLO 8192
#define SVHI 16384
#define SVLO 24576
#define ATTN_SMEM (STAGE0 + 2 * STG_SZ)
#define NCHUNK 32

__device__ __forceinline__ void attn_issue(u32 stg, int kbase, int t,
        const __nv_bfloat16* khi, const __nv_bfloat16* klo,
        const __nv_bfloat16* vthi, const __nv_bfloat16* vtlo) {
#pragma unroll
    for (int it = 0; it < 2; ++it) {
        int slot = t + it * 256;               // 512 slots: 64 rows x 8 cols
        int row  = slot >> 3, c = slot & 7;
        u32 dk = stg + SKHI + (u32)(row * 128) + (u32)((c * 16) ^ ((row & 7) << 4));
        size_t so = (size_t)(kbase + row) * 64 + c * 8;
        cpa16(dk,                 khi + so);
        cpa16(dk + (SKLO - SKHI), klo + so);
    }
#pragma unroll
    for (int it = 0; it < 2; ++it) {
        int slot = t + it * 256;               // 64 d-rows x 8 cols of 16B
        int row  = slot >> 3, c = slot & 7;
        u32 dv = stg + SVHI + (u32)(row * 128) + (u32)((c * 16) ^ ((row & 7) << 4));
        size_t so = (size_t)row * 2048 + kbase + c * 8;
        cpa16(dv,                 vthi + so);
        cpa16(dv + (SVLO - SVHI), vtlo + so);
    }
}

__global__ void __launch_bounds__(256, 2) attn_mma(const int* __restrict__ mask) {
    extern __shared__ __align__(1024) char smem[];
    const u32 sb = smem_u32(smem);
    const int t  = threadIdx.x, lane = t & 31, w = t >> 5;
    const int g  = lane >> 2, tg = lane & 3;
    const int lr = lane & 15, chi = lane >> 4;
    const int bh = blockIdx.y;
    const int b  = bh / Hh, h = bh - b * Hh;
    const int qbase = blockIdx.x * 128;
    const int qw = w * 16;

    const __nv_bfloat16* qhi  = g_qhi  + (size_t)bh * 2048 * 64;
    const __nv_bfloat16* qlo  = g_qlo  + (size_t)bh * 2048 * 64;
    const __nv_bfloat16* khi  = g_khi  + (size_t)bh * 2048 * 64;
    const __nv_bfloat16* klo  = g_klo  + (size_t)bh * 2048 * 64;
    const __nv_bfloat16* vthi = g_vthi + (size_t)bh * 64 * 2048;
    const __nv_bfloat16* vtlo = g_vtlo + (size_t)bh * 64 * 2048;

    // prologue: Q tiles (128 rows) + chunks 0,1
#pragma unroll
    for (int it = 0; it < 4; ++it) {
        int slot = t + it * 256;
        int row  = slot >> 3, c = slot & 7;
        u32 dq = sb + AQHI + (u32)(row * 128) + (u32)((c * 16) ^ ((row & 7) << 4));
        size_t so = (size_t)(qbase + row) * 64 + c * 8;
        cpa16(dq,                 qhi + so);
        cpa16(dq + (AQLO - AQHI), qlo + so);
    }
    attn_issue(sb + STAGE0, 0, t, khi, klo, vthi, vtlo);
    CP_COMMIT();
    attn_issue(sb + STAGE0 + STG_SZ, 64, t, khi, klo, vthi, vtlo);
    CP_COMMIT();

    float O[8][4];
#pragma unroll
    for (int i = 0; i < 8; i++)
#pragma unroll
        for (int j = 0; j < 4; j++) O[i][j] = 0.f;
    float mm0 = -1e30f, mm1 = -1e30f, ll0 = 0.f, ll1 = 0.f;
    u32 qh[4][4], ql[4][4];

    const int mrow0 = (qbase + qw + g) * 2048;
    const int mrow1 = mrow0 + 8 * 2048;

    for (int kc = 0; kc < NCHUNK; ++kc) {
        const int kbase = kc * 64;
        const u32 stg = sb + STAGE0 + (u32)((kc & 1) * STG_SZ);
        if (kc < NCHUNK - 1) { CP_WAIT(1); } else { CP_WAIT(0); }
        __syncthreads();

        if (kc == 0) {
            int row = qw + lr;
            u32 xq = (u32)((row & 7) << 4);
#pragma unroll
            for (int ks = 0; ks < 4; ++ks) {
                u32 cb = (u32)((ks * 32 + chi * 16)) ^ xq;
                u32 ra = sb + AQHI + (u32)(row * 128) + cb;
                ldm4(qh[ks][0], qh[ks][1], qh[ks][2], qh[ks][3], ra);
                ldm4(ql[ks][0], ql[ks][1], ql[ks][2], ql[ks][3], ra + (AQLO - AQHI));
            }
        }

        // ---- S = Q K^T : 3 passes, ks outer / jn inner (chain distance 8) ----
        float S[8][4];
#pragma unroll
        for (int i = 0; i < 8; i++)
#pragma unroll
            for (int j = 0; j < 4; j++) S[i][j] = 0.f;

#pragma unroll
        for (int pass = 0; pass < 3; ++pass) {
            const u32 kb = stg + ((pass == 1) ? SKLO : SKHI);
            const u32 (*aq)[4] = (pass == 2) ? ql : qh;
#pragma unroll
            for (int ks = 0; ks < 4; ++ks) {
#pragma unroll
                for (int jn = 0; jn < 4; ++jn) {
                    int rowb = jn * 16 + lr;
                    u32 b0, b1, b2, b3;
                    ldm4(b0, b1, b2, b3, kb + (u32)(rowb * 128) +
                         (((u32)(ks * 32 + chi * 16)) ^ (u32)((rowb & 7) << 4)));
                    mma16816(S[2 * jn],     aq[ks], b0, b2);
                    mma16816(S[2 * jn + 1], aq[ks], b1, b3);
                }
            }
        }

        // ---- mask + online softmax (64 cols) ----
        float rmax0 = -1e30f, rmax1 = -1e30f;
#pragma unroll
        for (int nf = 0; nf < 8; ++nf) {
            int col = kbase + nf * 8 + tg * 2;
            int2 mk0 = *(const int2*)(mask + mrow0 + col);
            int2 mk1 = *(const int2*)(mask + mrow1 + col);
            S[nf][0] += (float)mk0.x * MC_CONST;
            S[nf][1] += (float)mk0.y * MC_CONST;
            S[nf][2] += (float)mk1.x * MC_CONST;
            S[nf][3] += (float)mk1.y * MC_CONST;
            rmax0 = fmaxf(rmax0, fmaxf(S[nf][0], S[nf][1]));
            rmax1 = fmaxf(rmax1, fmaxf(S[nf][2], S[nf][3]));
        }
#pragma unroll
        for (int off = 1; off <= 2; off <<= 1) {
            rmax0 = fmaxf(rmax0, __shfl_xor_sync(0xffffffffu, rmax0, off));
            rmax1 = fmaxf(rmax1, __shfl_xor_sync(0xffffffffu, rmax1, off));
        }
        float mn0 = fmaxf(mm0, rmax0), mn1 = fmaxf(mm1, rmax1);
        float al0 = ex2(mm0 - mn0),    al1 = ex2(mm1 - mn1);
        mm0 = mn0; mm1 = mn1;
        float rs0 = 0.f, rs1 = 0.f;
#pragma unroll
        for (int nf = 0; nf < 8; ++nf) {
            S[nf][0] = exp2p(S[nf][0] - mn0);
            S[nf][1] = exp2p(S[nf][1] - mn0);
            S[nf][2] = exp2p(S[nf][2] - mn1);
            S[nf][3] = exp2p(S[nf][3] - mn1);
            rs0 += S[nf][0] + S[nf][1];
            rs1 += S[nf][2] + S[nf][3];
        }
#pragma unroll
        for (int off = 1; off <= 2; off <<= 1) {
            rs0 += __shfl_xor_sync(0xffffffffu, rs0, off);
            rs1 += __shfl_xor_sync(0xffffffffu, rs1, off);
        }
        ll0 = ll0 * al0 + rs0;
        ll1 = ll1 * al1 + rs1;
#pragma unroll
        for (int nf = 0; nf < 8; ++nf) {
            O[nf][0] *= al0; O[nf][1] *= al0;
            O[nf][2] *= al1; O[nf][3] *= al1;
        }

        // ---- O += P V : split P once, 3 passes, ks2 outer / jd inner ----
        u32 Phi[4][4], Plo[4][4];
#pragma unroll
        for (int ks2 = 0; ks2 < 4; ++ks2) {
            split2(S[2 * ks2][0],     S[2 * ks2][1],     Phi[ks2][0], Plo[ks2][0]);
            split2(S[2 * ks2][2],     S[2 * ks2][3],     Phi[ks2][1], Plo[ks2][1]);
            split2(S[2 * ks2 + 1][0], S[2 * ks2 + 1][1], Phi[ks2][2], Plo[ks2][2]);
            split2(S[2 * ks2 + 1][2], S[2 * ks2 + 1][3], Phi[ks2][3], Plo[ks2][3]);
        }
#pragma unroll
        for (int pass = 0; pass < 3; ++pass) {
            const u32 vb = stg + ((pass == 1) ? SVLO : SVHI);
            const u32 (*ap)[4] = (pass == 2) ? Plo : Phi;
#pragma unroll
            for (int ks2 = 0; ks2 < 4; ++ks2) {
#pragma unroll
                for (int jd = 0; jd < 4; ++jd) {
                    int rowd = jd * 16 + lr;
                    u32 b0, b1, b2, b3;
                    ldm4(b0, b1, b2, b3, vb + (u32)(rowd * 128) +
                         (((u32)(ks2 * 32 + chi * 16)) ^ (u32)((rowd & 7) << 4)));
                    mma16816(O[2 * jd],     ap[ks2], b0, b2);
                    mma16816(O[2 * jd + 1], ap[ks2], b1, b3);
                }
            }
        }

        __syncthreads();
        if (kc + 2 < NCHUNK) {
            attn_issue(stg, (kc + 2) * 64, t, khi, klo, vthi, vtlo);
            CP_COMMIT();
        }
    }

    // ---- write O / l to g_ao ----
    float inv0 = 1.f / ll0, inv1 = 1.f / ll1;
    float* o0p = g_ao + (size_t)(b * Nseq + qbase + qw + g) * Cdim + h * 64;
    float* o1p = o0p + (size_t)8 * Cdim;
#pragma unroll
    for (int nf = 0; nf < 8; ++nf) {
        int col = nf * 8 + tg * 2;
        float2 v0; v0.x = O[nf][0] * inv0; v0.y = O[nf][1] * inv0;
        float2 v1; v1.x = O[nf][2] * inv1; v1.y = O[nf][3] * inv1;
        *(float2*)(o0p + col) = v0;
        *(float2*)(o1p + col) = v1;
    }
}

// ---------------------------------------------------------------------------
extern "C" void kernel_launch(void* const* d_in, const int* in_sizes, int n_in,
                              void* d_out, int out_size) {
    const float* x      = (const float*)d_in[0];
    const int*   mask   = (const int*)  d_in[1];
    const float* qkv_w  = (const float*)d_in[2];
    const float* proj_w = (const float*)d_in[3];
    const float* proj_b = (const float*)d_in[4];
    float*       out    = (float*)d_out;

    cudaFuncSetAttribute(attn_mma,
                         cudaFuncAttributeMaxDynamicSharedMemorySize, ATTN_SMEM);
    cudaFuncSetAttribute(gemm_mma<1>,
                         cudaFuncAttributeMaxDynamicSharedMemorySize, GEMM_SMEM);
    cudaFuncSetAttribute(gemm_mma<2>,
                         cudaFuncAttributeMaxDynamicSharedMemorySize, GEMM_SMEM);

    gemm_mma<1><<<dim3(2304 / 128, 8192 / 128), 256, GEMM_SMEM>>>(x, qkv_w, nullptr,
                                                                  nullptr, 2304);
    attn_mma<<<dim3(Nseq / 128, Bc * Hh), 256, ATTN_SMEM>>>(mask);
    gemm_mma<2><<<dim3(768 / 128, 8192 / 128), 256, GEMM_SMEM>>>(nullptr, proj_w, proj_b,
                                                                 out, 768);
}

// round 12
// speedup vs baseline: 1.2978x; 1.2978x over previous
// v12: GEMM BK=32, hi|lo packed per 128B row, 64KB smem -> 2 CTA/SM @256 thr.
// Attention is v8 verbatim (best passing). 512-thread variant abandoned.
#include <cuda_runtime.h>
#include <cuda_bf16.h>
#include <cstdint>

#define Bc   4
#define Nseq 2048
#define Cdim 768
#define Hh   12
#define Dd   64

using u64 = unsigned long long;
using u32 = unsigned int;

#define QS_CONST 92.33248261972106f    // 64 * log2(e)
#define MC_CONST -1442695.040888963f   // -1e6 * log2(e)

__device__ __forceinline__ float ex2(float x) {
    float y; asm("ex2.approx.f32 %0,%1;" : "=f"(y) : "f"(x)); return y;
}
__device__ __forceinline__ u32 smem_u32(const void* p) {
    u32 a; asm("{ .reg .u64 t; cvta.to.shared.u64 t, %1; cvt.u32.u64 %0, t; }" : "=r"(a) : "l"(p));
    return a;
}
__device__ __forceinline__ void ldm4(u32& r0, u32& r1, u32& r2, u32& r3, u32 addr) {
    asm volatile("ldmatrix.sync.aligned.m8n8.x4.shared.b16 {%0,%1,%2,%3},[%4];"
        : "=r"(r0), "=r"(r1), "=r"(r2), "=r"(r3) : "r"(addr));
}
__device__ __forceinline__ void mma16816(float* c, const u32* a, u32 b0, u32 b1) {
    asm volatile("mma.sync.aligned.m16n8k16.row.col.f32.bf16.bf16.f32 "
        "{%0,%1,%2,%3},{%4,%5,%6,%7},{%8,%9},{%0,%1,%2,%3};"
        : "+f"(c[0]), "+f"(c[1]), "+f"(c[2]), "+f"(c[3])
        : "r"(a[0]), "r"(a[1]), "r"(a[2]), "r"(a[3]), "r"(b0), "r"(b1));
}
__device__ __forceinline__ u32 pkbf(float lo, float hi) {
    u32 r; asm("cvt.rn.bf16x2.f32 %0,%1,%2;" : "=r"(r) : "f"(hi), "f"(lo)); return r;
}
__device__ __forceinline__ void split2(float x, float y, u32& hi, u32& lo) {
    hi = pkbf(x, y);
    float hx = __int_as_float(hi << 16);
    float hy = __int_as_float(hi & 0xFFFF0000u);
    lo = pkbf(x - hx, y - hy);
}
__device__ __forceinline__ float exp2p(float x) {
    x = fmaxf(x, -126.0f);
    float t = x + 12582912.0f;
    int  k  = __float_as_int(t) - 0x4B400000;
    float xf = x - (t - 12582912.0f);
    float p = 0.0096180f;
    p = p * xf + 0.0555041f;
    p = p * xf + 0.2402265f;
    p = p * xf + 0.6931472f;
    p = p * xf + 1.0f;
    return p * __int_as_float((k + 127) << 23);
}
__device__ __forceinline__ void cpa16(u32 dst, const void* src) {
    asm volatile("cp.async.cg.shared.global [%0], [%1], 16;" :: "r"(dst), "l"(src) : "memory");
}
#define CP_COMMIT() asm volatile("cp.async.commit_group;" ::: "memory")
#define CP_WAIT(n)  asm volatile("cp.async.wait_group %0;" :: "n"(n) : "memory")

// Scratch: bf16 hi/lo QKV (Q pre-scaled; V pre-transposed) + fp32 attn out
__device__ __nv_bfloat16 g_qhi[(size_t)48 * 2048 * 64];
__device__ __nv_bfloat16 g_qlo[(size_t)48 * 2048 * 64];
__device__ __nv_bfloat16 g_khi[(size_t)48 * 2048 * 64];
__device__ __nv_bfloat16 g_klo[(size_t)48 * 2048 * 64];
__device__ __nv_bfloat16 g_vthi[(size_t)48 * 64 * 2048];   // [bh][d][n]
__device__ __nv_bfloat16 g_vtlo[(size_t)48 * 64 * 2048];
__device__ float g_ao[(size_t)Bc * Nseq * Cdim];           // [B][N][C]

// ===========================================================================
// HMMA split-bf16 GEMM NT, 256 threads, BK=32, hi|lo packed per 128B row.
// Stage = A(16KB) + B(16KB) = 32KB; 2 stages = 64KB -> 2 CTA/SM.
// Row layout: [32 bf16 hi | 32 bf16 lo] = 128B; same SW128 swizzle as v8.
// ===========================================================================
#define MTILE_B 16384          // one matrix (A or B): 128 rows x 128B
#define STG_B32 32768          // stage: A + B
#define GEMM_SMEM (2 * STG_B32)

__device__ __forceinline__ void fill32(const float* __restrict__ src, char* dst,
                                       int kbase, int t) {
#pragma unroll
    for (int it = 0; it < 4; ++it) {
        int slot = t + it * 256;       // 0..1023
        int row  = slot >> 3;          // 0..127
        int c4   = (slot & 7) << 2;    // 0..28
        float4 v = *(const float4*)(src + (size_t)row * 768 + kbase + c4);
        u32 h01, l01, h23, l23;
        split2(v.x, v.y, h01, l01);
        split2(v.z, v.w, h23, l23);
        u32 offh = (u32)(row * 128 + c4 * 2);        // hi: cols 0..63
        u32 offl = offh + 64;                        // lo: cols 64..127
        u32 swh = offh ^ ((offh >> 3) & 0x70);
        u32 swl = offl ^ ((offl >> 3) & 0x70);
        uint2 uh; uh.x = h01; uh.y = h23;
        uint2 ul; ul.x = l01; ul.y = l23;
        *(uint2*)(dst + swh) = uh;
        *(uint2*)(dst + swl) = ul;
    }
}

template<int MODE>
__global__ void __launch_bounds__(256, 2) gemm_mma(const float* __restrict__ A_,
                                                   const float* __restrict__ Bw,
                                                   const float* __restrict__ bias,
                                                   float* __restrict__ C, int Nn) {
    extern __shared__ __align__(1024) char smem[];
    const u32 sb   = smem_u32(smem);
    const int t    = threadIdx.x, lane = t & 31, wid = t >> 5;
    const int i0   = blockIdx.y * 128, j0 = blockIdx.x * 128;
    const float* __restrict__ Arow = ((MODE == 2) ? g_ao : A_) + (size_t)i0 * 768;
    const float* __restrict__ Brow = Bw + (size_t)j0 * 768;

    const int m0  = (wid >> 2) * 64;
    const int n0  = (wid & 3) * 32;
    const int lr  = lane & 15;
    const int chi = lane >> 4;
    const u32 xorv = (u32)((lane & 7) << 4);

    float acc[4][4][4];
#pragma unroll
    for (int i = 0; i < 4; i++)
#pragma unroll
        for (int j = 0; j < 4; j++)
#pragma unroll
            for (int k = 0; k < 4; k++) acc[i][j][k] = 0.f;

    fill32(Arow, smem + 0,       0, t);
    fill32(Brow, smem + MTILE_B, 0, t);
    __syncthreads();

    for (int kc = 0; kc < 24; ++kc) {
        const int st = kc & 1;
        if (kc + 1 < 24) {
            char* nb = smem + (st ^ 1) * STG_B32;
            fill32(Arow, nb,           (kc + 1) * 32, t);
            fill32(Brow, nb + MTILE_B, (kc + 1) * 32, t);
        }
        __syncthreads();

        const u32 base = sb + (u32)(st * STG_B32);
#pragma unroll
        for (int s = 0; s < 2; ++s) {
            const u32 csel   = (u32)((2 * s + chi) << 4);   // 0,16,32,48
            const u32 ct_h   = csel ^ xorv;
            const u32 ct_l   = (64u + csel) ^ xorv;
            u32 ah[4][4], al[4][4];
#pragma unroll
            for (int i = 0; i < 4; i++) {
                u32 ra = base + (u32)((m0 + i * 16 + lr) * 128);
                ldm4(ah[i][0], ah[i][1], ah[i][2], ah[i][3], ra + ct_h);
                ldm4(al[i][0], al[i][1], al[i][2], al[i][3], ra + ct_l);
            }
            u32 bh[8], bl[8];
#pragma unroll
            for (int j = 0; j < 2; j++) {
                u32 rb = base + MTILE_B + (u32)((n0 + j * 16 + lr) * 128);
                ldm4(bh[j * 4 + 0], bh[j * 4 + 1], bh[j * 4 + 2], bh[j * 4 + 3], rb + ct_h);
                ldm4(bl[j * 4 + 0], bl[j * 4 + 1], bl[j * 4 + 2], bl[j * 4 + 3], rb + ct_l);
            }
#pragma unroll
            for (int i = 0; i < 4; i++)
#pragma unroll
                for (int jj = 0; jj < 4; jj++) {
                    int j4 = (jj >> 1) * 4 + (jj & 1);
                    mma16816(acc[i][jj], ah[i], bh[j4], bh[j4 + 2]);
                    mma16816(acc[i][jj], ah[i], bl[j4], bl[j4 + 2]);
                    mma16816(acc[i][jj], al[i], bh[j4], bh[j4 + 2]);
                }
        }
        __syncthreads();
    }

#pragma unroll
    for (int i = 0; i < 4; i++) {
        int r0 = m0 + i * 16 + (lane >> 2);
#pragma unroll
        for (int jj = 0; jj < 4; jj++) {
            int col = n0 + jj * 8 + 2 * (lane & 3);
#pragma unroll
            for (int half = 0; half < 2; half++) {
                int gi = i0 + r0 + half * 8;
                int gj = j0 + col;
                float2 v;
                v.x = acc[i][jj][half * 2 + 0];
                v.y = acc[i][jj][half * 2 + 1];
                if (MODE == 1) {
                    int b = gi >> 11, n = gi & 2047;
                    int three = gj / 768, rem = gj - three * 768;
                    int hh = rem >> 6, d = rem & 63;
                    int bhI = b * 12 + hh;
                    if (three < 2) {
                        float sc = (three == 0) ? QS_CONST : 1.0f;
                        u32 hi, lo;
                        split2(v.x * sc, v.y * sc, hi, lo);
                        size_t idx = ((size_t)bhI * 2048 + n) * 64 + d;
                        __nv_bfloat16* ph = (three == 0) ? g_qhi : g_khi;
                        __nv_bfloat16* pl = (three == 0) ? g_qlo : g_klo;
                        *(u32*)(ph + idx) = hi;
                        *(u32*)(pl + idx) = lo;
                    } else {
                        size_t b0 = ((size_t)bhI * 64 + d) * 2048 + n;
                        __nv_bfloat16 hx = __float2bfloat16(v.x);
                        g_vthi[b0] = hx;
                        g_vtlo[b0] = __float2bfloat16(v.x - __bfloat162float(hx));
                        __nv_bfloat16 hy = __float2bfloat16(v.y);
                        g_vthi[b0 + 2048] = hy;
                        g_vtlo[b0 + 2048] = __float2bfloat16(v.y - __bfloat162float(hy));
                    }
                } else {
                    v.x += bias[gj];
                    v.y += bias[gj + 1];
                    *(float2*)(C + (size_t)gi * Nn + gj) = v;
                }
            }
        }
    }
}

// ===========================================================================
// HMMA flash attention — v8 verbatim (best passing: ~720us).
// ===========================================================================
#define AQHI 0
#define AQLO 16384
#define STAGE0 32768
#define STG_SZ 65536
#define SKHI 0
#define SKLO 16384
#define SVHI 32768
#define SVLO 49152
#define ATTN_SMEM (STAGE0 + 2 * STG_SZ)

__device__ __forceinline__ void attn_issue(u32 stg, int kbase, int t,
        const __nv_bfloat16* khi, const __nv_bfloat16* klo,
        const __nv_bfloat16* vthi, const __nv_bfloat16* vtlo) {
#pragma unroll
    for (int it = 0; it < 4; ++it) {
        int slot = t + it * 256;           // 1024 slots
        int row  = slot >> 3, c = slot & 7;
        u32 dk = stg + SKHI + (u32)(row * 128) + (u32)((c * 16) ^ ((row & 7) << 4));
        size_t so = (size_t)(kbase + row) * 64 + c * 8;
        cpa16(dk,                 khi + so);
        cpa16(dk + (SKLO - SKHI), klo + so);
    }
#pragma unroll
    for (int it = 0; it < 4; ++it) {
        int slot = t + it * 256;
        int row  = slot >> 4, c = slot & 15;   // 64 rows x 16 chunks
        u32 dv = stg + SVHI + (u32)(row * 256) + (u32)((c * 16) ^ ((row & 7) << 4));
        size_t so = (size_t)row * 2048 + kbase + c * 8;
        cpa16(dv,                 vthi + so);
        cpa16(dv + (SVLO - SVHI), vtlo + so);
    }
}

__global__ void __launch_bounds__(256) attn_mma(const int* __restrict__ mask) {
    extern __shared__ __align__(1024) char smem[];
    const u32 sb = smem_u32(smem);
    const int t  = threadIdx.x, lane = t & 31, w = t >> 5;
    const int g  = lane >> 2, tg = lane & 3;
    const int lr = lane & 15, chi = lane >> 4;
    const int bh = blockIdx.y;
    const int b  = bh / Hh, h = bh - b * Hh;
    const int qbase = blockIdx.x * 128;
    const int qw = w * 16;

    const __nv_bfloat16* qhi  = g_qhi  + (size_t)bh * 2048 * 64;
    const __nv_bfloat16* qlo  = g_qlo  + (size_t)bh * 2048 * 64;
    const __nv_bfloat16* khi  = g_khi  + (size_t)bh * 2048 * 64;
    const __nv_bfloat16* klo  = g_klo  + (size_t)bh * 2048 * 64;
    const __nv_bfloat16* vthi = g_vthi + (size_t)bh * 64 * 2048;
    const __nv_bfloat16* vtlo = g_vtlo + (size_t)bh * 64 * 2048;

#pragma unroll
    for (int it = 0; it < 4; ++it) {
        int slot = t + it * 256;
        int row  = slot >> 3, c = slot & 7;
        u32 dq = sb + AQHI + (u32)(row * 128) + (u32)((c * 16) ^ ((row & 7) << 4));
        size_t so = (size_t)(qbase + row) * 64 + c * 8;
        cpa16(dq,                 qhi + so);
        cpa16(dq + (AQLO - AQHI), qlo + so);
    }
    attn_issue(sb + STAGE0, 0, t, khi, klo, vthi, vtlo);
    CP_COMMIT();
    attn_issue(sb + STAGE0 + STG_SZ, 128, t, khi, klo, vthi, vtlo);
    CP_COMMIT();

    float O[8][4];
#pragma unroll
    for (int i = 0; i < 8; i++)
#pragma unroll
        for (int j = 0; j < 4; j++) O[i][j] = 0.f;
    float mm0 = -1e30f, mm1 = -1e30f, ll0 = 0.f, ll1 = 0.f;
    u32 qh[4][4], ql[4][4];

    const int mrow0 = (qbase + qw + g) * 2048;
    const int mrow1 = mrow0 + 8 * 2048;

    for (int kc = 0; kc < 16; ++kc) {
        const int kbase = kc * 128;
        const u32 stg = sb + STAGE0 + (u32)((kc & 1) * STG_SZ);
        if (kc < 15) { CP_WAIT(1); } else { CP_WAIT(0); }
        __syncthreads();

        if (kc == 0) {
            int row = qw + lr;
            u32 xq = (u32)((row & 7) << 4);
#pragma unroll
            for (int ks = 0; ks < 4; ++ks) {
                u32 cb = (u32)((ks * 32 + chi * 16)) ^ xq;
                u32 ra = sb + AQHI + (u32)(row * 128) + cb;
                ldm4(qh[ks][0], qh[ks][1], qh[ks][2], qh[ks][3], ra);
                ldm4(ql[ks][0], ql[ks][1], ql[ks][2], ql[ks][3], ra + (AQLO - AQHI));
            }
        }

        float S[16][4];
#pragma unroll
        for (int i = 0; i < 16; i++)
#pragma unroll
            for (int j = 0; j < 4; j++) S[i][j] = 0.f;

#pragma unroll
        for (int jn = 0; jn < 8; ++jn) {
            int rowb = jn * 16 + lr;
            u32 rba  = stg + SKHI + (u32)(rowb * 128);
            u32 xorb = (u32)((rowb & 7) << 4);
#pragma unroll
            for (int ks = 0; ks < 4; ++ks) {
                u32 off = ((u32)(ks * 32 + chi * 16)) ^ xorb;
                u32 bh0, bh1, bh2, bh3, bl0, bl1, bl2, bl3;
                ldm4(bh0, bh1, bh2, bh3, rba + off);
                ldm4(bl0, bl1, bl2, bl3, rba + (SKLO - SKHI) + off);
                mma16816(S[2 * jn],     qh[ks], bh0, bh2);
                mma16816(S[2 * jn + 1], qh[ks], bh1, bh3);
                mma16816(S[2 * jn],     qh[ks], bl0, bl2);
                mma16816(S[2 * jn + 1], qh[ks], bl1, bl3);
                mma16816(S[2 * jn],     ql[ks], bh0, bh2);
                mma16816(S[2 * jn + 1], ql[ks], bh1, bh3);
            }
        }

        float rmax0 = -1e30f, rmax1 = -1e30f;
#pragma unroll
        for (int nf = 0; nf < 16; ++nf) {
            int col = kbase + nf * 8 + tg * 2;
            int2 mk0 = *(const int2*)(mask + mrow0 + col);
            int2 mk1 = *(const int2*)(mask + mrow1 + col);
            S[nf][0] += (float)mk0.x * MC_CONST;
            S[nf][1] += (float)mk0.y * MC_CONST;
            S[nf][2] += (float)mk1.x * MC_CONST;
            S[nf][3] += (float)mk1.y * MC_CONST;
            rmax0 = fmaxf(rmax0, fmaxf(S[nf][0], S[nf][1]));
            rmax1 = fmaxf(rmax1, fmaxf(S[nf][2], S[nf][3]));
        }
#pragma unroll
        for (int off = 1; off <= 2; off <<= 1) {
            rmax0 = fmaxf(rmax0, __shfl_xor_sync(0xffffffffu, rmax0, off));
            rmax1 = fmaxf(rmax1, __shfl_xor_sync(0xffffffffu, rmax1, off));
        }
        float mn0 = fmaxf(mm0, rmax0), mn1 = fmaxf(mm1, rmax1);
        float al0 = ex2(mm0 - mn0),    al1 = ex2(mm1 - mn1);
        mm0 = mn0; mm1 = mn1;
        float rs0 = 0.f, rs1 = 0.f;
#pragma unroll
        for (int nf = 0; nf < 16; ++nf) {
            S[nf][0] = exp2p(S[nf][0] - mn0);
            S[nf][1] = exp2p(S[nf][1] - mn0);
            S[nf][2] = exp2p(S[nf][2] - mn1);
            S[nf][3] = exp2p(S[nf][3] - mn1);
            rs0 += S[nf][0] + S[nf][1];
            rs1 += S[nf][2] + S[nf][3];
        }
#pragma unroll
        for (int off = 1; off <= 2; off <<= 1) {
            rs0 += __shfl_xor_sync(0xffffffffu, rs0, off);
            rs1 += __shfl_xor_sync(0xffffffffu, rs1, off);
        }
        ll0 = ll0 * al0 + rs0;
        ll1 = ll1 * al1 + rs1;
#pragma unroll
        for (int nf = 0; nf < 8; ++nf) {
            O[nf][0] *= al0; O[nf][1] *= al0;
            O[nf][2] *= al1; O[nf][3] *= al1;
        }

#pragma unroll
        for (int ks2 = 0; ks2 < 8; ++ks2) {
            u32 ahi[4], alo[4];
            split2(S[2 * ks2][0],     S[2 * ks2][1],     ahi[0], alo[0]);
            split2(S[2 * ks2][2],     S[2 * ks2][3],     ahi[1], alo[1]);
            split2(S[2 * ks2 + 1][0], S[2 * ks2 + 1][1], ahi[2], alo[2]);
            split2(S[2 * ks2 + 1][2], S[2 * ks2 + 1][3], ahi[3], alo[3]);
#pragma unroll
            for (int jd = 0; jd < 4; ++jd) {
                int rowd = jd * 16 + lr;
                u32 aoff = (u32)(rowd * 256) +
                           (((u32)(ks2 * 32 + chi * 16)) ^ (u32)((rowd & 7) << 4));
                u32 b0, b1, b2, b3;
                ldm4(b0, b1, b2, b3, stg + SVHI + aoff);
                mma16816(O[2 * jd],     ahi, b0, b2);
                mma16816(O[2 * jd + 1], ahi, b1, b3);
                mma16816(O[2 * jd],     alo, b0, b2);
                mma16816(O[2 * jd + 1], alo, b1, b3);
                u32 c0, c1, c2, c3;
                ldm4(c0, c1, c2, c3, stg + SVLO + aoff);
                mma16816(O[2 * jd],     ahi, c0, c2);
                mma16816(O[2 * jd + 1], ahi, c1, c3);
            }
        }

        __syncthreads();
        if (kc + 2 < 16) {
            attn_issue(stg, (kc + 2) * 128, t, khi, klo, vthi, vtlo);
            CP_COMMIT();
        }
    }

    float inv0 = 1.f / ll0, inv1 = 1.f / ll1;
    float* o0p = g_ao + (size_t)(b * Nseq + qbase + qw + g) * Cdim + h * 64;
    float* o1p = o0p + (size_t)8 * Cdim;
#pragma unroll
    for (int nf = 0; nf < 8; ++nf) {
        int col = nf * 8 + tg * 2;
        float2 v0; v0.x = O[nf][0] * inv0; v0.y = O[nf][1] * inv0;
        float2 v1; v1.x = O[nf][2] * inv1; v1.y = O[nf][3] * inv1;
        *(float2*)(o0p + col) = v0;
        *(float2*)(o1p + col) = v1;
    }
}

// ---------------------------------------------------------------------------
extern "C" void kernel_launch(void* const* d_in, const int* in_sizes, int n_in,
                              void* d_out, int out_size) {
    const float* x      = (const float*)d_in[0];
    const int*   mask   = (const int*)  d_in[1];
    const float* qkv_w  = (const float*)d_in[2];
    const float* proj_w = (const float*)d_in[3];
    const float* proj_b = (const float*)d_in[4];
    float*       out    = (float*)d_out;

    cudaFuncSetAttribute(attn_mma,
                         cudaFuncAttributeMaxDynamicSharedMemorySize, ATTN_SMEM);
    cudaFuncSetAttribute(gemm_mma<1>,
                         cudaFuncAttributeMaxDynamicSharedMemorySize, GEMM_SMEM);
    cudaFuncSetAttribute(gemm_mma<2>,
                         cudaFuncAttributeMaxDynamicSharedMemorySize, GEMM_SMEM);

    gemm_mma<1><<<dim3(2304 / 128, 8192 / 128), 256, GEMM_SMEM>>>(x, qkv_w, nullptr,
                                                                  nullptr, 2304);
    attn_mma<<<dim3(Nseq / 128, Bc * Hh), 256, ATTN_SMEM>>>(mask);
    gemm_mma<2><<<dim3(768 / 128, 8192 / 128), 256, GEMM_SMEM>>>(nullptr, proj_w, proj_b,
                                                                 out, 768);
}

// round 13
// speedup vs baseline: 1.4456x; 1.1139x over previous
// v13: attention at 2 CTA/SM via Q-buffer aliasing + single-V (96KB smem),
// softmax per 64-key half-chunk (register diet). GEMMs = v12 verbatim.
#include <cuda_runtime.h>
#include <cuda_bf16.h>
#include <cstdint>

#define Bc   4
#define Nseq 2048
#define Cdim 768
#define Hh   12
#define Dd   64

using u64 = unsigned long long;
using u32 = unsigned int;

#define QS_CONST 92.33248261972106f    // 64 * log2(e)
#define MC_CONST -1442695.040888963f   // -1e6 * log2(e)

__device__ __forceinline__ float ex2(float x) {
    float y; asm("ex2.approx.f32 %0,%1;" : "=f"(y) : "f"(x)); return y;
}
__device__ __forceinline__ u32 smem_u32(const void* p) {
    u32 a; asm("{ .reg .u64 t; cvta.to.shared.u64 t, %1; cvt.u32.u64 %0, t; }" : "=r"(a) : "l"(p));
    return a;
}
__device__ __forceinline__ void ldm4(u32& r0, u32& r1, u32& r2, u32& r3, u32 addr) {
    asm volatile("ldmatrix.sync.aligned.m8n8.x4.shared.b16 {%0,%1,%2,%3},[%4];"
        : "=r"(r0), "=r"(r1), "=r"(r2), "=r"(r3) : "r"(addr));
}
__device__ __forceinline__ void mma16816(float* c, const u32* a, u32 b0, u32 b1) {
    asm volatile("mma.sync.aligned.m16n8k16.row.col.f32.bf16.bf16.f32 "
        "{%0,%1,%2,%3},{%4,%5,%6,%7},{%8,%9},{%0,%1,%2,%3};"
        : "+f"(c[0]), "+f"(c[1]), "+f"(c[2]), "+f"(c[3])
        : "r"(a[0]), "r"(a[1]), "r"(a[2]), "r"(a[3]), "r"(b0), "r"(b1));
}
__device__ __forceinline__ u32 pkbf(float lo, float hi) {
    u32 r; asm("cvt.rn.bf16x2.f32 %0,%1,%2;" : "=r"(r) : "f"(hi), "f"(lo)); return r;
}
__device__ __forceinline__ void split2(float x, float y, u32& hi, u32& lo) {
    hi = pkbf(x, y);
    float hx = __int_as_float(hi << 16);
    float hy = __int_as_float(hi & 0xFFFF0000u);
    lo = pkbf(x - hx, y - hy);
}
__device__ __forceinline__ float exp2p(float x) {
    x = fmaxf(x, -126.0f);
    float t = x + 12582912.0f;
    int  k  = __float_as_int(t) - 0x4B400000;
    float xf = x - (t - 12582912.0f);
    float p = 0.0096180f;
    p = p * xf + 0.0555041f;
    p = p * xf + 0.2402265f;
    p = p * xf + 0.6931472f;
    p = p * xf + 1.0f;
    return p * __int_as_float((k + 127) << 23);
}
__device__ __forceinline__ void cpa16(u32 dst, const void* src) {
    asm volatile("cp.async.cg.shared.global [%0], [%1], 16;" :: "r"(dst), "l"(src) : "memory");
}
#define CP_COMMIT() asm volatile("cp.async.commit_group;" ::: "memory")
#define CP_WAIT(n)  asm volatile("cp.async.wait_group %0;" :: "n"(n) : "memory")

// Scratch: bf16 hi/lo QKV (Q pre-scaled; V pre-transposed) + fp32 attn out
__device__ __nv_bfloat16 g_qhi[(size_t)48 * 2048 * 64];
__device__ __nv_bfloat16 g_qlo[(size_t)48 * 2048 * 64];
__device__ __nv_bfloat16 g_khi[(size_t)48 * 2048 * 64];
__device__ __nv_bfloat16 g_klo[(size_t)48 * 2048 * 64];
__device__ __nv_bfloat16 g_vthi[(size_t)48 * 64 * 2048];   // [bh][d][n]
__device__ __nv_bfloat16 g_vtlo[(size_t)48 * 64 * 2048];
__device__ float g_ao[(size_t)Bc * Nseq * Cdim];           // [B][N][C]

// ===========================================================================
// HMMA split-bf16 GEMM NT — v12 verbatim (passing, 331us / ~110us).
// ===========================================================================
#define MTILE_B 16384
#define STG_B32 32768
#define GEMM_SMEM (2 * STG_B32)

__device__ __forceinline__ void fill32(const float* __restrict__ src, char* dst,
                                       int kbase, int t) {
#pragma unroll
    for (int it = 0; it < 4; ++it) {
        int slot = t + it * 256;
        int row  = slot >> 3;
        int c4   = (slot & 7) << 2;
        float4 v = *(const float4*)(src + (size_t)row * 768 + kbase + c4);
        u32 h01, l01, h23, l23;
        split2(v.x, v.y, h01, l01);
        split2(v.z, v.w, h23, l23);
        u32 offh = (u32)(row * 128 + c4 * 2);
        u32 offl = offh + 64;
        u32 swh = offh ^ ((offh >> 3) & 0x70);
        u32 swl = offl ^ ((offl >> 3) & 0x70);
        uint2 uh; uh.x = h01; uh.y = h23;
        uint2 ul; ul.x = l01; ul.y = l23;
        *(uint2*)(dst + swh) = uh;
        *(uint2*)(dst + swl) = ul;
    }
}

template<int MODE>
__global__ void __launch_bounds__(256, 2) gemm_mma(const float* __restrict__ A_,
                                                   const float* __restrict__ Bw,
                                                   const float* __restrict__ bias,
                                                   float* __restrict__ C, int Nn) {
    extern __shared__ __align__(1024) char smem[];
    const u32 sb   = smem_u32(smem);
    const int t    = threadIdx.x, lane = t & 31, wid = t >> 5;
    const int i0   = blockIdx.y * 128, j0 = blockIdx.x * 128;
    const float* __restrict__ Arow = ((MODE == 2) ? g_ao : A_) + (size_t)i0 * 768;
    const float* __restrict__ Brow = Bw + (size_t)j0 * 768;

    const int m0  = (wid >> 2) * 64;
    const int n0  = (wid & 3) * 32;
    const int lr  = lane & 15;
    const int chi = lane >> 4;
    const u32 xorv = (u32)((lane & 7) << 4);

    float acc[4][4][4];
#pragma unroll
    for (int i = 0; i < 4; i++)
#pragma unroll
        for (int j = 0; j < 4; j++)
#pragma unroll
            for (int k = 0; k < 4; k++) acc[i][j][k] = 0.f;

    fill32(Arow, smem + 0,       0, t);
    fill32(Brow, smem + MTILE_B, 0, t);
    __syncthreads();

    for (int kc = 0; kc < 24; ++kc) {
        const int st = kc & 1;
        if (kc + 1 < 24) {
            char* nb = smem + (st ^ 1) * STG_B32;
            fill32(Arow, nb,           (kc + 1) * 32, t);
            fill32(Brow, nb + MTILE_B, (kc + 1) * 32, t);
        }
        __syncthreads();

        const u32 base = sb + (u32)(st * STG_B32);
#pragma unroll
        for (int s = 0; s < 2; ++s) {
            const u32 csel = (u32)((2 * s + chi) << 4);
            const u32 ct_h = csel ^ xorv;
            const u32 ct_l = (64u + csel) ^ xorv;
            u32 ah[4][4], al[4][4];
#pragma unroll
            for (int i = 0; i < 4; i++) {
                u32 ra = base + (u32)((m0 + i * 16 + lr) * 128);
                ldm4(ah[i][0], ah[i][1], ah[i][2], ah[i][3], ra + ct_h);
                ldm4(al[i][0], al[i][1], al[i][2], al[i][3], ra + ct_l);
            }
            u32 bh[8], bl[8];
#pragma unroll
            for (int j = 0; j < 2; j++) {
                u32 rb = base + MTILE_B + (u32)((n0 + j * 16 + lr) * 128);
                ldm4(bh[j * 4 + 0], bh[j * 4 + 1], bh[j * 4 + 2], bh[j * 4 + 3], rb + ct_h);
                ldm4(bl[j * 4 + 0], bl[j * 4 + 1], bl[j * 4 + 2], bl[j * 4 + 3], rb + ct_l);
            }
#pragma unroll
            for (int i = 0; i < 4; i++)
#pragma unroll
                for (int jj = 0; jj < 4; jj++) {
                    int j4 = (jj >> 1) * 4 + (jj & 1);
                    mma16816(acc[i][jj], ah[i], bh[j4], bh[j4 + 2]);
                    mma16816(acc[i][jj], ah[i], bl[j4], bl[j4 + 2]);
                    mma16816(acc[i][jj], al[i], bh[j4], bh[j4 + 2]);
                }
        }
        __syncthreads();
    }

#pragma unroll
    for (int i = 0; i < 4; i++) {
        int r0 = m0 + i * 16 + (lane >> 2);
#pragma unroll
        for (int jj = 0; jj < 4; jj++) {
            int col = n0 + jj * 8 + 2 * (lane & 3);
#pragma unroll
            for (int half = 0; half < 2; half++) {
                int gi = i0 + r0 + half * 8;
                int gj = j0 + col;
                float2 v;
                v.x = acc[i][jj][half * 2 + 0];
                v.y = acc[i][jj][half * 2 + 1];
                if (MODE == 1) {
                    int b = gi >> 11, n = gi & 2047;
                    int three = gj / 768, rem = gj - three * 768;
                    int hh = rem >> 6, d = rem & 63;
                    int bhI = b * 12 + hh;
                    if (three < 2) {
                        float sc = (three == 0) ? QS_CONST : 1.0f;
                        u32 hi, lo;
                        split2(v.x * sc, v.y * sc, hi, lo);
                        size_t idx = ((size_t)bhI * 2048 + n) * 64 + d;
                        __nv_bfloat16* ph = (three == 0) ? g_qhi : g_khi;
                        __nv_bfloat16* pl = (three == 0) ? g_qlo : g_klo;
                        *(u32*)(ph + idx) = hi;
                        *(u32*)(pl + idx) = lo;
                    } else {
                        size_t b0 = ((size_t)bhI * 64 + d) * 2048 + n;
                        __nv_bfloat16 hx = __float2bfloat16(v.x);
                        g_vthi[b0] = hx;
                        g_vtlo[b0] = __float2bfloat16(v.x - __bfloat162float(hx));
                        __nv_bfloat16 hy = __float2bfloat16(v.y);
                        g_vthi[b0 + 2048] = hy;
                        g_vtlo[b0 + 2048] = __float2bfloat16(v.y - __bfloat162float(hy));
                    }
                } else {
                    v.x += bias[gj];
                    v.y += bias[gj + 1];
                    *(float2*)(C + (size_t)gi * Nn + gj) = v;
                }
            }
        }
    }
}

// ===========================================================================
// HMMA flash attention v13: 96KB smem (K x2 double-buffered, single V buffer
// aliased with Q), softmax per 64-key half-chunk. 2 CTA/SM.
// ===========================================================================
#define KB0   0
#define KB1   32768
#define VBUF  65536            // Vhi @65536, Vlo @81920; Q aliases this region
#define ATTN_SMEM 98304

__device__ __forceinline__ void issue_k(u32 dst, int kbase, int t,
        const __nv_bfloat16* khi, const __nv_bfloat16* klo) {
#pragma unroll
    for (int it = 0; it < 4; ++it) {
        int slot = t + it * 256;           // 1024 slots: 128 rows x 8 cols
        int row  = slot >> 3, c = slot & 7;
        u32 dk = dst + (u32)(row * 128) + (u32)((c * 16) ^ ((row & 7) << 4));
        size_t so = (size_t)(kbase + row) * 64 + c * 8;
        cpa16(dk,          khi + so);
        cpa16(dk + 16384,  klo + so);
    }
}
__device__ __forceinline__ void issue_v(u32 dst, int kbase, int t,
        const __nv_bfloat16* vthi, const __nv_bfloat16* vtlo) {
#pragma unroll
    for (int it = 0; it < 4; ++it) {
        int slot = t + it * 256;           // 64 d-rows x 16 chunks
        int row  = slot >> 4, c = slot & 15;
        u32 dv = dst + (u32)(row * 256) + (u32)((c * 16) ^ ((row & 7) << 4));
        size_t so = (size_t)row * 2048 + kbase + c * 8;
        cpa16(dv,          vthi + so);
        cpa16(dv + 16384,  vtlo + so);
    }
}

__global__ void __launch_bounds__(256, 2) attn_mma(const int* __restrict__ mask) {
    extern __shared__ __align__(1024) char smem[];
    const u32 sb = smem_u32(smem);
    const int t  = threadIdx.x, lane = t & 31, w = t >> 5;
    const int g  = lane >> 2, tg = lane & 3;
    const int lr = lane & 15, chi = lane >> 4;
    const int bh = blockIdx.y;
    const int b  = bh / Hh, h = bh - b * Hh;
    const int qbase = blockIdx.x * 128;
    const int qw = w * 16;

    const __nv_bfloat16* qhi  = g_qhi  + (size_t)bh * 2048 * 64;
    const __nv_bfloat16* qlo  = g_qlo  + (size_t)bh * 2048 * 64;
    const __nv_bfloat16* khi  = g_khi  + (size_t)bh * 2048 * 64;
    const __nv_bfloat16* klo  = g_klo  + (size_t)bh * 2048 * 64;
    const __nv_bfloat16* vthi = g_vthi + (size_t)bh * 64 * 2048;
    const __nv_bfloat16* vtlo = g_vtlo + (size_t)bh * 64 * 2048;

    // --- prologue: Q into VBUF region, consume to registers, then reuse ---
#pragma unroll
    for (int it = 0; it < 4; ++it) {
        int slot = t + it * 256;
        int row  = slot >> 3, c = slot & 7;
        u32 dq = sb + VBUF + (u32)(row * 128) + (u32)((c * 16) ^ ((row & 7) << 4));
        size_t so = (size_t)(qbase + row) * 64 + c * 8;
        cpa16(dq,          qhi + so);
        cpa16(dq + 16384,  qlo + so);
    }
    CP_COMMIT();
    CP_WAIT(0);
    __syncthreads();

    u32 qh[4][4], ql[4][4];
    {
        int row = qw + lr;
        u32 xq = (u32)((row & 7) << 4);
#pragma unroll
        for (int ks = 0; ks < 4; ++ks) {
            u32 cb = (u32)((ks * 32 + chi * 16)) ^ xq;
            u32 ra = sb + VBUF + (u32)(row * 128) + cb;
            ldm4(qh[ks][0], qh[ks][1], qh[ks][2], qh[ks][3], ra);
            ldm4(ql[ks][0], ql[ks][1], ql[ks][2], ql[ks][3], ra + 16384);
        }
    }
    __syncthreads();   // all warps done reading Q before V0 overwrites

    issue_k(sb + KB0, 0, t, khi, klo);
    CP_COMMIT();
    issue_v(sb + VBUF, 0, t, vthi, vtlo);
    CP_COMMIT();
    issue_k(sb + KB1, 128, t, khi, klo);
    CP_COMMIT();

    float O[8][4];
#pragma unroll
    for (int i = 0; i < 8; i++)
#pragma unroll
        for (int j = 0; j < 4; j++) O[i][j] = 0.f;
    float mm0 = -1e30f, mm1 = -1e30f, ll0 = 0.f, ll1 = 0.f;

    const int mrow0 = (qbase + qw + g) * 2048;
    const int mrow1 = mrow0 + 8 * 2048;

    for (int kc = 0; kc < 16; ++kc) {
        const int kbase = kc * 128;
        const u32 kb = sb + (u32)((kc & 1) ? KB1 : KB0);
        if (kc < 15) { CP_WAIT(1); } else { CP_WAIT(0); }
        __syncthreads();

#pragma unroll
        for (int half = 0; half < 2; ++half) {
            const int koff = half * 64;
            // ---- S = Q K^T over 64 keys ----
            float S[8][4];
#pragma unroll
            for (int i = 0; i < 8; i++)
#pragma unroll
                for (int j = 0; j < 4; j++) S[i][j] = 0.f;
#pragma unroll
            for (int jn = 0; jn < 4; ++jn) {
                int rowb = koff + jn * 16 + lr;
                u32 rba  = kb + (u32)(rowb * 128);
                u32 xorb = (u32)((rowb & 7) << 4);
#pragma unroll
                for (int ks = 0; ks < 4; ++ks) {
                    u32 off = ((u32)(ks * 32 + chi * 16)) ^ xorb;
                    u32 bh0, bh1, bh2, bh3, bl0, bl1, bl2, bl3;
                    ldm4(bh0, bh1, bh2, bh3, rba + off);
                    ldm4(bl0, bl1, bl2, bl3, rba + 16384 + off);
                    mma16816(S[2 * jn],     qh[ks], bh0, bh2);
                    mma16816(S[2 * jn + 1], qh[ks], bh1, bh3);
                    mma16816(S[2 * jn],     qh[ks], bl0, bl2);
                    mma16816(S[2 * jn + 1], qh[ks], bl1, bl3);
                    mma16816(S[2 * jn],     ql[ks], bh0, bh2);
                    mma16816(S[2 * jn + 1], ql[ks], bh1, bh3);
                }
            }

            // ---- mask + online softmax over these 64 keys ----
            float rmax0 = -1e30f, rmax1 = -1e30f;
#pragma unroll
            for (int nf = 0; nf < 8; ++nf) {
                int col = kbase + koff + nf * 8 + tg * 2;
                int2 mk0 = *(const int2*)(mask + mrow0 + col);
                int2 mk1 = *(const int2*)(mask + mrow1 + col);
                S[nf][0] += (float)mk0.x * MC_CONST;
                S[nf][1] += (float)mk0.y * MC_CONST;
                S[nf][2] += (float)mk1.x * MC_CONST;
                S[nf][3] += (float)mk1.y * MC_CONST;
                rmax0 = fmaxf(rmax0, fmaxf(S[nf][0], S[nf][1]));
                rmax1 = fmaxf(rmax1, fmaxf(S[nf][2], S[nf][3]));
            }
#pragma unroll
            for (int off = 1; off <= 2; off <<= 1) {
                rmax0 = fmaxf(rmax0, __shfl_xor_sync(0xffffffffu, rmax0, off));
                rmax1 = fmaxf(rmax1, __shfl_xor_sync(0xffffffffu, rmax1, off));
            }
            float mn0 = fmaxf(mm0, rmax0), mn1 = fmaxf(mm1, rmax1);
            float al0 = ex2(mm0 - mn0),    al1 = ex2(mm1 - mn1);
            mm0 = mn0; mm1 = mn1;
            float rs0 = 0.f, rs1 = 0.f;
#pragma unroll
            for (int nf = 0; nf < 8; ++nf) {
                S[nf][0] = exp2p(S[nf][0] - mn0);
                S[nf][1] = exp2p(S[nf][1] - mn0);
                S[nf][2] = exp2p(S[nf][2] - mn1);
                S[nf][3] = exp2p(S[nf][3] - mn1);
                rs0 += S[nf][0] + S[nf][1];
                rs1 += S[nf][2] + S[nf][3];
            }
#pragma unroll
            for (int off = 1; off <= 2; off <<= 1) {
                rs0 += __shfl_xor_sync(0xffffffffu, rs0, off);
                rs1 += __shfl_xor_sync(0xffffffffu, rs1, off);
            }
            ll0 = ll0 * al0 + rs0;
            ll1 = ll1 * al1 + rs1;
#pragma unroll
            for (int nf = 0; nf < 8; ++nf) {
                O[nf][0] *= al0; O[nf][1] *= al0;
                O[nf][2] *= al1; O[nf][3] *= al1;
            }

            // ---- O += P V over these 64 keys ----
#pragma unroll
            for (int ks2 = 0; ks2 < 4; ++ks2) {
                u32 ahi[4], alo[4];
                split2(S[2 * ks2][0],     S[2 * ks2][1],     ahi[0], alo[0]);
                split2(S[2 * ks2][2],     S[2 * ks2][3],     ahi[1], alo[1]);
                split2(S[2 * ks2 + 1][0], S[2 * ks2 + 1][1], ahi[2], alo[2]);
                split2(S[2 * ks2 + 1][2], S[2 * ks2 + 1][3], ahi[3], alo[3]);
#pragma unroll
                for (int jd = 0; jd < 4; ++jd) {
                    int rowd = jd * 16 + lr;
                    u32 aoff = (u32)(rowd * 256) +
                               (((u32)(koff * 2 + ks2 * 32 + chi * 16)) ^ (u32)((rowd & 7) << 4));
                    u32 b0, b1, b2, b3;
                    ldm4(b0, b1, b2, b3, sb + VBUF + aoff);
                    mma16816(O[2 * jd],     ahi, b0, b2);
                    mma16816(O[2 * jd + 1], ahi, b1, b3);
                    mma16816(O[2 * jd],     alo, b0, b2);
                    mma16816(O[2 * jd + 1], alo, b1, b3);
                    u32 c0, c1, c2, c3;
                    ldm4(c0, c1, c2, c3, sb + VBUF + 16384 + aoff);
                    mma16816(O[2 * jd],     ahi, c0, c2);
                    mma16816(O[2 * jd + 1], ahi, c1, c3);
                }
            }
        }

        __syncthreads();   // all warps done with V and this K stage
        if (kc + 1 < 16) {
            issue_v(sb + VBUF, (kc + 1) * 128, t, vthi, vtlo);
            CP_COMMIT();
        }
        if (kc + 2 < 16) {
            issue_k(kb, (kc + 2) * 128, t, khi, klo);
            CP_COMMIT();
        }
    }

    // ---- write O / l to g_ao ----
    float inv0 = 1.f / ll0, inv1 = 1.f / ll1;
    float* o0p = g_ao + (size_t)(b * Nseq + qbase + qw + g) * Cdim + h * 64;
    float* o1p = o0p + (size_t)8 * Cdim;
#pragma unroll
    for (int nf = 0; nf < 8; ++nf) {
        int col = nf * 8 + tg * 2;
        float2 v0; v0.x = O[nf][0] * inv0; v0.y = O[nf][1] * inv0;
        float2 v1; v1.x = O[nf][2] * inv1; v1.y = O[nf][3] * inv1;
        *(float2*)(o0p + col) = v0;
        *(float2*)(o1p + col) = v1;
    }
}

// ---------------------------------------------------------------------------
extern "C" void kernel_launch(void* const* d_in, const int* in_sizes, int n_in,
                              void* d_out, int out_size) {
    const float* x      = (const float*)d_in[0];
    const int*   mask   = (const int*)  d_in[1];
    const float* qkv_w  = (const float*)d_in[2];
    const float* proj_w = (const float*)d_in[3];
    const float* proj_b = (const float*)d_in[4];
    float*       out    = (float*)d_out;

    cudaFuncSetAttribute(attn_mma,
                         cudaFuncAttributeMaxDynamicSharedMemorySize, ATTN_SMEM);
    cudaFuncSetAttribute(gemm_mma<1>,
                         cudaFuncAttributeMaxDynamicSharedMemorySize, GEMM_SMEM);
    cudaFuncSetAttribute(gemm_mma<2>,
                         cudaFuncAttributeMaxDynamicSharedMemorySize, GEMM_SMEM);

    gemm_mma<1><<<dim3(2304 / 128, 8192 / 128), 256, GEMM_SMEM>>>(x, qkv_w, nullptr,
                                                                  nullptr, 2304);
    attn_mma<<<dim3(Nseq / 128, Bc * Hh), 256, ATTN_SMEM>>>(mask);
    gemm_mma<2><<<dim3(768 / 128, 8192 / 128), 256, GEMM_SMEM>>>(nullptr, proj_w, proj_b,
                                                                 out, 768);
}

// round 15
// speedup vs baseline: 1.5586x; 1.0781x over previous
// v15: v14 (prepacked-operand GEMM) with cudaGetSymbolAddress removed —
// kernels reference __device__ globals directly via template selection.
// Compute loops byte-identical to passing v13/v12.
#include <cuda_runtime.h>
#include <cuda_bf16.h>
#include <cstdint>

#define Bc   4
#define Nseq 2048
#define Cdim 768
#define Hh   12
#define Dd   64

using u64 = unsigned long long;
using u32 = unsigned int;

#define QS_CONST 92.33248261972106f    // 64 * log2(e)
#define MC_CONST -1442695.040888963f   // -1e6 * log2(e)

__device__ __forceinline__ float ex2(float x) {
    float y; asm("ex2.approx.f32 %0,%1;" : "=f"(y) : "f"(x)); return y;
}
__device__ __forceinline__ u32 smem_u32(const void* p) {
    u32 a; asm("{ .reg .u64 t; cvta.to.shared.u64 t, %1; cvt.u32.u64 %0, t; }" : "=r"(a) : "l"(p));
    return a;
}
__device__ __forceinline__ void ldm4(u32& r0, u32& r1, u32& r2, u32& r3, u32 addr) {
    asm volatile("ldmatrix.sync.aligned.m8n8.x4.shared.b16 {%0,%1,%2,%3},[%4];"
        : "=r"(r0), "=r"(r1), "=r"(r2), "=r"(r3) : "r"(addr));
}
__device__ __forceinline__ void mma16816(float* c, const u32* a, u32 b0, u32 b1) {
    asm volatile("mma.sync.aligned.m16n8k16.row.col.f32.bf16.bf16.f32 "
        "{%0,%1,%2,%3},{%4,%5,%6,%7},{%8,%9},{%0,%1,%2,%3};"
        : "+f"(c[0]), "+f"(c[1]), "+f"(c[2]), "+f"(c[3])
        : "r"(a[0]), "r"(a[1]), "r"(a[2]), "r"(a[3]), "r"(b0), "r"(b1));
}
__device__ __forceinline__ u32 pkbf(float lo, float hi) {
    u32 r; asm("cvt.rn.bf16x2.f32 %0,%1,%2;" : "=r"(r) : "f"(hi), "f"(lo)); return r;
}
__device__ __forceinline__ void split2(float x, float y, u32& hi, u32& lo) {
    hi = pkbf(x, y);
    float hx = __int_as_float(hi << 16);
    float hy = __int_as_float(hi & 0xFFFF0000u);
    lo = pkbf(x - hx, y - hy);
}
__device__ __forceinline__ float exp2p(float x) {
    x = fmaxf(x, -126.0f);
    float t = x + 12582912.0f;
    int  k  = __float_as_int(t) - 0x4B400000;
    float xf = x - (t - 12582912.0f);
    float p = 0.0096180f;
    p = p * xf + 0.0555041f;
    p = p * xf + 0.2402265f;
    p = p * xf + 0.6931472f;
    p = p * xf + 1.0f;
    return p * __int_as_float((k + 127) << 23);
}
__device__ __forceinline__ void cpa16(u32 dst, const void* src) {
    asm volatile("cp.async.cg.shared.global [%0], [%1], 16;" :: "r"(dst), "l"(src) : "memory");
}
#define CP_COMMIT() asm volatile("cp.async.commit_group;" ::: "memory")
#define CP_WAIT(n)  asm volatile("cp.async.wait_group %0;" :: "n"(n) : "memory")

// ---------- scratch (all referenced directly; no symbol-address queries) ----
// packed rows: [row][24 chunks][32 hi bf16 | 32 lo bf16] -> 1536 bf16 per row
__device__ __nv_bfloat16 g_xpk[(size_t)8192 * 1536];
__device__ __nv_bfloat16 g_wqkvpk[(size_t)2304 * 1536];
__device__ __nv_bfloat16 g_wprojpk[(size_t)768 * 1536];
__device__ __nv_bfloat16 g_aopk[(size_t)8192 * 1536];
// attention operands (bf16 hi/lo; Q pre-scaled; V pre-transposed)
__device__ __nv_bfloat16 g_qhi[(size_t)48 * 2048 * 64];
__device__ __nv_bfloat16 g_qlo[(size_t)48 * 2048 * 64];
__device__ __nv_bfloat16 g_khi[(size_t)48 * 2048 * 64];
__device__ __nv_bfloat16 g_klo[(size_t)48 * 2048 * 64];
__device__ __nv_bfloat16 g_vthi[(size_t)48 * 64 * 2048];   // [bh][d][n]
__device__ __nv_bfloat16 g_vtlo[(size_t)48 * 64 * 2048];

// ===========================================================================
// prepack: fp32 [rows][768] -> packed hi|lo rows. DST: 0=g_xpk 1=g_wqkvpk 2=g_wprojpk
// ===========================================================================
template<int DST>
__global__ void prepack(const float* __restrict__ src, int nrows) {
    int idx = blockIdx.x * 256 + threadIdx.x;      // one per 4 floats
    if (idx >= nrows * 192) return;
    __nv_bfloat16* dst = (DST == 0) ? g_xpk : (DST == 1) ? g_wqkvpk : g_wprojpk;
    int r = idx / 192, q = idx - r * 192;
    int col = q * 4;
    int chunk = col >> 5, pos = col & 31;
    float4 v = *(const float4*)(src + (size_t)r * 768 + col);
    u32 h01, l01, h23, l23;
    split2(v.x, v.y, h01, l01);
    split2(v.z, v.w, h23, l23);
    __nv_bfloat16* base = dst + (size_t)r * 1536 + chunk * 64 + pos;
    *(u32*)(base)      = h01; *(u32*)(base + 2)  = h23;
    *(u32*)(base + 32) = l01; *(u32*)(base + 34) = l23;
}

// ===========================================================================
// GEMM NT on prepacked operands (globals chosen by MODE). BK=32 chunk =
// 128B/row (hi|lo), cp.async double buffer, v12 compute/epilogue verbatim.
// 64KB smem -> 2 CTA/SM.
// ===========================================================================
#define MTILE_B 16384
#define STG_B32 32768
#define GEMM_SMEM (2 * STG_B32)

__device__ __forceinline__ void issue_g(u32 dst, const __nv_bfloat16* __restrict__ pk,
                                        int kc, int t) {
#pragma unroll
    for (int it = 0; it < 4; ++it) {
        int slot = t + it * 256;           // 1024: 128 rows x 8 granules
        int row  = slot >> 3, gg = slot & 7;
        u32 off = (u32)(row * 128 + gg * 16);
        u32 sw  = off ^ ((off >> 3) & 0x70);
        cpa16(dst + sw, (const char*)pk + (size_t)row * 3072 + kc * 128 + gg * 16);
    }
}

template<int MODE>
__global__ void __launch_bounds__(256, 2) gemm_mma(const float* __restrict__ bias,
                                                   float* __restrict__ C, int Nn) {
    extern __shared__ __align__(1024) char smem[];
    const u32 sb   = smem_u32(smem);
    const int t    = threadIdx.x, lane = t & 31, wid = t >> 5;
    const int i0   = blockIdx.y * 128, j0 = blockIdx.x * 128;
    const __nv_bfloat16* __restrict__ Ar =
        ((MODE == 1) ? g_xpk : g_aopk) + (size_t)i0 * 1536;
    const __nv_bfloat16* __restrict__ Br =
        ((MODE == 1) ? g_wqkvpk : g_wprojpk) + (size_t)j0 * 1536;

    const int m0  = (wid >> 2) * 64;
    const int n0  = (wid & 3) * 32;
    const int lr  = lane & 15;
    const int chi = lane >> 4;
    const u32 xorv = (u32)((lane & 7) << 4);

    float acc[4][4][4];
#pragma unroll
    for (int i = 0; i < 4; i++)
#pragma unroll
        for (int j = 0; j < 4; j++)
#pragma unroll
            for (int k = 0; k < 4; k++) acc[i][j][k] = 0.f;

    issue_g(sb + 0,       Ar, 0, t);
    issue_g(sb + MTILE_B, Br, 0, t);
    CP_COMMIT();
    issue_g(sb + STG_B32,           Ar, 1, t);
    issue_g(sb + STG_B32 + MTILE_B, Br, 1, t);
    CP_COMMIT();

    for (int kc = 0; kc < 24; ++kc) {
        const int st = kc & 1;
        if (kc < 23) { CP_WAIT(1); } else { CP_WAIT(0); }
        __syncthreads();

        const u32 base = sb + (u32)(st * STG_B32);
#pragma unroll
        for (int s = 0; s < 2; ++s) {
            const u32 csel = (u32)((2 * s + chi) << 4);
            const u32 ct_h = csel ^ xorv;
            const u32 ct_l = (64u + csel) ^ xorv;
            u32 ah[4][4], al[4][4];
#pragma unroll
            for (int i = 0; i < 4; i++) {
                u32 ra = base + (u32)((m0 + i * 16 + lr) * 128);
                ldm4(ah[i][0], ah[i][1], ah[i][2], ah[i][3], ra + ct_h);
                ldm4(al[i][0], al[i][1], al[i][2], al[i][3], ra + ct_l);
            }
            u32 bh[8], bl[8];
#pragma unroll
            for (int j = 0; j < 2; j++) {
                u32 rb = base + MTILE_B + (u32)((n0 + j * 16 + lr) * 128);
                ldm4(bh[j * 4 + 0], bh[j * 4 + 1], bh[j * 4 + 2], bh[j * 4 + 3], rb + ct_h);
                ldm4(bl[j * 4 + 0], bl[j * 4 + 1], bl[j * 4 + 2], bl[j * 4 + 3], rb + ct_l);
            }
#pragma unroll
            for (int i = 0; i < 4; i++)
#pragma unroll
                for (int jj = 0; jj < 4; jj++) {
                    int j4 = (jj >> 1) * 4 + (jj & 1);
                    mma16816(acc[i][jj], ah[i], bh[j4], bh[j4 + 2]);
                    mma16816(acc[i][jj], ah[i], bl[j4], bl[j4 + 2]);
                    mma16816(acc[i][jj], al[i], bh[j4], bh[j4 + 2]);
                }
        }
        __syncthreads();
        if (kc + 2 < 24) {
            issue_g(sb + (u32)(st * STG_B32),           Ar, kc + 2, t);
            issue_g(sb + (u32)(st * STG_B32) + MTILE_B, Br, kc + 2, t);
            CP_COMMIT();
        }
    }

#pragma unroll
    for (int i = 0; i < 4; i++) {
        int r0 = m0 + i * 16 + (lane >> 2);
#pragma unroll
        for (int jj = 0; jj < 4; jj++) {
            int col = n0 + jj * 8 + 2 * (lane & 3);
#pragma unroll
            for (int half = 0; half < 2; half++) {
                int gi = i0 + r0 + half * 8;
                int gj = j0 + col;
                float2 v;
                v.x = acc[i][jj][half * 2 + 0];
                v.y = acc[i][jj][half * 2 + 1];
                if (MODE == 1) {
                    int b = gi >> 11, n = gi & 2047;
                    int three = gj / 768, rem = gj - three * 768;
                    int hh = rem >> 6, d = rem & 63;
                    int bhI = b * 12 + hh;
                    if (three < 2) {
                        float sc = (three == 0) ? QS_CONST : 1.0f;
                        u32 hi, lo;
                        split2(v.x * sc, v.y * sc, hi, lo);
                        size_t idx = ((size_t)bhI * 2048 + n) * 64 + d;
                        __nv_bfloat16* ph = (three == 0) ? g_qhi : g_khi;
                        __nv_bfloat16* pl = (three == 0) ? g_qlo : g_klo;
                        *(u32*)(ph + idx) = hi;
                        *(u32*)(pl + idx) = lo;
                    } else {
                        size_t b0 = ((size_t)bhI * 64 + d) * 2048 + n;
                        __nv_bfloat16 hx = __float2bfloat16(v.x);
                        g_vthi[b0] = hx;
                        g_vtlo[b0] = __float2bfloat16(v.x - __bfloat162float(hx));
                        __nv_bfloat16 hy = __float2bfloat16(v.y);
                        g_vthi[b0 + 2048] = hy;
                        g_vtlo[b0 + 2048] = __float2bfloat16(v.y - __bfloat162float(hy));
                    }
                } else {
                    v.x += bias[gj];
                    v.y += bias[gj + 1];
                    *(float2*)(C + (size_t)gi * Nn + gj) = v;
                }
            }
        }
    }
}

// ===========================================================================
// HMMA flash attention v13 (passing) — epilogue writes packed g_aopk.
// ===========================================================================
#define KB0   0
#define KB1   32768
#define VBUF  65536
#define ATTN_SMEM 98304

__device__ __forceinline__ void issue_k(u32 dst, int kbase, int t,
        const __nv_bfloat16* khi, const __nv_bfloat16* klo) {
#pragma unroll
    for (int it = 0; it < 4; ++it) {
        int slot = t + it * 256;
        int row  = slot >> 3, c = slot & 7;
        u32 dk = dst + (u32)(row * 128) + (u32)((c * 16) ^ ((row & 7) << 4));
        size_t so = (size_t)(kbase + row) * 64 + c * 8;
        cpa16(dk,          khi + so);
        cpa16(dk + 16384,  klo + so);
    }
}
__device__ __forceinline__ void issue_v(u32 dst, int kbase, int t,
        const __nv_bfloat16* vthi, const __nv_bfloat16* vtlo) {
#pragma unroll
    for (int it = 0; it < 4; ++it) {
        int slot = t + it * 256;
        int row  = slot >> 4, c = slot & 15;
        u32 dv = dst + (u32)(row * 256) + (u32)((c * 16) ^ ((row & 7) << 4));
        size_t so = (size_t)row * 2048 + kbase + c * 8;
        cpa16(dv,          vthi + so);
        cpa16(dv + 16384,  vtlo + so);
    }
}

__global__ void __launch_bounds__(256, 2) attn_mma(const int* __restrict__ mask) {
    extern __shared__ __align__(1024) char smem[];
    const u32 sb = smem_u32(smem);
    const int t  = threadIdx.x, lane = t & 31, w = t >> 5;
    const int g  = lane >> 2, tg = lane & 3;
    const int lr = lane & 15, chi = lane >> 4;
    const int bh = blockIdx.y;
    const int b  = bh / Hh, h = bh - b * Hh;
    const int qbase = blockIdx.x * 128;
    const int qw = w * 16;

    const __nv_bfloat16* qhi  = g_qhi  + (size_t)bh * 2048 * 64;
    const __nv_bfloat16* qlo  = g_qlo  + (size_t)bh * 2048 * 64;
    const __nv_bfloat16* khi  = g_khi  + (size_t)bh * 2048 * 64;
    const __nv_bfloat16* klo  = g_klo  + (size_t)bh * 2048 * 64;
    const __nv_bfloat16* vthi = g_vthi + (size_t)bh * 64 * 2048;
    const __nv_bfloat16* vtlo = g_vtlo + (size_t)bh * 64 * 2048;

#pragma unroll
    for (int it = 0; it < 4; ++it) {
        int slot = t + it * 256;
        int row  = slot >> 3, c = slot & 7;
        u32 dq = sb + VBUF + (u32)(row * 128) + (u32)((c * 16) ^ ((row & 7) << 4));
        size_t so = (size_t)(qbase + row) * 64 + c * 8;
        cpa16(dq,          qhi + so);
        cpa16(dq + 16384,  qlo + so);
    }
    CP_COMMIT();
    CP_WAIT(0);
    __syncthreads();

    u32 qh[4][4], ql[4][4];
    {
        int row = qw + lr;
        u32 xq = (u32)((row & 7) << 4);
#pragma unroll
        for (int ks = 0; ks < 4; ++ks) {
            u32 cb = (u32)((ks * 32 + chi * 16)) ^ xq;
            u32 ra = sb + VBUF + (u32)(row * 128) + cb;
            ldm4(qh[ks][0], qh[ks][1], qh[ks][2], qh[ks][3], ra);
            ldm4(ql[ks][0], ql[ks][1], ql[ks][2], ql[ks][3], ra + 16384);
        }
    }
    __syncthreads();

    issue_k(sb + KB0, 0, t, khi, klo);
    CP_COMMIT();
    issue_v(sb + VBUF, 0, t, vthi, vtlo);
    CP_COMMIT();
    issue_k(sb + KB1, 128, t, khi, klo);
    CP_COMMIT();

    float O[8][4];
#pragma unroll
    for (int i = 0; i < 8; i++)
#pragma unroll
        for (int j = 0; j < 4; j++) O[i][j] = 0.f;
    float mm0 = -1e30f, mm1 = -1e30f, ll0 = 0.f, ll1 = 0.f;

    const int mrow0 = (qbase + qw + g) * 2048;
    const int mrow1 = mrow0 + 8 * 2048;

    for (int kc = 0; kc < 16; ++kc) {
        const int kbase = kc * 128;
        const u32 kb = sb + (u32)((kc & 1) ? KB1 : KB0);
        if (kc < 15) { CP_WAIT(1); } else { CP_WAIT(0); }
        __syncthreads();

#pragma unroll
        for (int half = 0; half < 2; ++half) {
            const int koff = half * 64;
            float S[8][4];
#pragma unroll
            for (int i = 0; i < 8; i++)
#pragma unroll
                for (int j = 0; j < 4; j++) S[i][j] = 0.f;
#pragma unroll
            for (int jn = 0; jn < 4; ++jn) {
                int rowb = koff + jn * 16 + lr;
                u32 rba  = kb + (u32)(rowb * 128);
                u32 xorb = (u32)((rowb & 7) << 4);
#pragma unroll
                for (int ks = 0; ks < 4; ++ks) {
                    u32 off = ((u32)(ks * 32 + chi * 16)) ^ xorb;
                    u32 bh0, bh1, bh2, bh3, bl0, bl1, bl2, bl3;
                    ldm4(bh0, bh1, bh2, bh3, rba + off);
                    ldm4(bl0, bl1, bl2, bl3, rba + 16384 + off);
                    mma16816(S[2 * jn],     qh[ks], bh0, bh2);
                    mma16816(S[2 * jn + 1], qh[ks], bh1, bh3);
                    mma16816(S[2 * jn],     qh[ks], bl0, bl2);
                    mma16816(S[2 * jn + 1], qh[ks], bl1, bl3);
                    mma16816(S[2 * jn],     ql[ks], bh0, bh2);
                    mma16816(S[2 * jn + 1], ql[ks], bh1, bh3);
                }
            }

            float rmax0 = -1e30f, rmax1 = -1e30f;
#pragma unroll
            for (int nf = 0; nf < 8; ++nf) {
                int col = kbase + koff + nf * 8 + tg * 2;
                int2 mk0 = *(const int2*)(mask + mrow0 + col);
                int2 mk1 = *(const int2*)(mask + mrow1 + col);
                S[nf][0] += (float)mk0.x * MC_CONST;
                S[nf][1] += (float)mk0.y * MC_CONST;
                S[nf][2] += (float)mk1.x * MC_CONST;
                S[nf][3] += (float)mk1.y * MC_CONST;
                rmax0 = fmaxf(rmax0, fmaxf(S[nf][0], S[nf][1]));
                rmax1 = fmaxf(rmax1, fmaxf(S[nf][2], S[nf][3]));
            }
#pragma unroll
            for (int off = 1; off <= 2; off <<= 1) {
                rmax0 = fmaxf(rmax0, __shfl_xor_sync(0xffffffffu, rmax0, off));
                rmax1 = fmaxf(rmax1, __shfl_xor_sync(0xffffffffu, rmax1, off));
            }
            float mn0 = fmaxf(mm0, rmax0), mn1 = fmaxf(mm1, rmax1);
            float al0 = ex2(mm0 - mn0),    al1 = ex2(mm1 - mn1);
            mm0 = mn0; mm1 = mn1;
            float rs0 = 0.f, rs1 = 0.f;
#pragma unroll
            for (int nf = 0; nf < 8; ++nf) {
                S[nf][0] = exp2p(S[nf][0] - mn0);
                S[nf][1] = exp2p(S[nf][1] - mn0);
                S[nf][2] = exp2p(S[nf][2] - mn1);
                S[nf][3] = exp2p(S[nf][3] - mn1);
                rs0 += S[nf][0] + S[nf][1];
                rs1 += S[nf][2] + S[nf][3];
            }
#pragma unroll
            for (int off = 1; off <= 2; off <<= 1) {
                rs0 += __shfl_xor_sync(0xffffffffu, rs0, off);
                rs1 += __shfl_xor_sync(0xffffffffu, rs1, off);
            }
            ll0 = ll0 * al0 + rs0;
            ll1 = ll1 * al1 + rs1;
#pragma unroll
            for (int nf = 0; nf < 8; ++nf) {
                O[nf][0] *= al0; O[nf][1] *= al0;
                O[nf][2] *= al1; O[nf][3] *= al1;
            }

#pragma unroll
            for (int ks2 = 0; ks2 < 4; ++ks2) {
                u32 ahi[4], alo[4];
                split2(S[2 * ks2][0],     S[2 * ks2][1],     ahi[0], alo[0]);
                split2(S[2 * ks2][2],     S[2 * ks2][3],     ahi[1], alo[1]);
                split2(S[2 * ks2 + 1][0], S[2 * ks2 + 1][1], ahi[2], alo[2]);
                split2(S[2 * ks2 + 1][2], S[2 * ks2 + 1][3], ahi[3], alo[3]);
#pragma unroll
                for (int jd = 0; jd < 4; ++jd) {
                    int rowd = jd * 16 + lr;
                    u32 aoff = (u32)(rowd * 256) +
                               (((u32)(koff * 2 + ks2 * 32 + chi * 16)) ^ (u32)((rowd & 7) << 4));
                    u32 b0, b1, b2, b3;
                    ldm4(b0, b1, b2, b3, sb + VBUF + aoff);
                    mma16816(O[2 * jd],     ahi, b0, b2);
                    mma16816(O[2 * jd + 1], ahi, b1, b3);
                    mma16816(O[2 * jd],     alo, b0, b2);
                    mma16816(O[2 * jd + 1], alo, b1, b3);
                    u32 c0, c1, c2, c3;
                    ldm4(c0, c1, c2, c3, sb + VBUF + 16384 + aoff);
                    mma16816(O[2 * jd],     ahi, c0, c2);
                    mma16816(O[2 * jd + 1], ahi, c1, c3);
                }
            }
        }

        __syncthreads();
        if (kc + 1 < 16) {
            issue_v(sb + VBUF, (kc + 1) * 128, t, vthi, vtlo);
            CP_COMMIT();
        }
        if (kc + 2 < 16) {
            issue_k(kb, (kc + 2) * 128, t, khi, klo);
            CP_COMMIT();
        }
    }

    // ---- write O (normalized) to packed g_aopk for GEMM2 ----
    float inv0 = 1.f / ll0, inv1 = 1.f / ll1;
    int row0 = b * Nseq + qbase + qw + g;
    int row1 = row0 + 8;
#pragma unroll
    for (int nf = 0; nf < 8; ++nf) {
        int col   = h * 64 + nf * 8 + tg * 2;
        int chunk = col >> 5, pos = col & 31;
        u32 hi, lo;
        split2(O[nf][0] * inv0, O[nf][1] * inv0, hi, lo);
        __nv_bfloat16* p0 = g_aopk + (size_t)row0 * 1536 + chunk * 64 + pos;
        *(u32*)p0        = hi;
        *(u32*)(p0 + 32) = lo;
        split2(O[nf][2] * inv1, O[nf][3] * inv1, hi, lo);
        __nv_bfloat16* p1 = g_aopk + (size_t)row1 * 1536 + chunk * 64 + pos;
        *(u32*)p1        = hi;
        *(u32*)(p1 + 32) = lo;
    }
}

// ---------------------------------------------------------------------------
extern "C" void kernel_launch(void* const* d_in, const int* in_sizes, int n_in,
                              void* d_out, int out_size) {
    const float* x      = (const float*)d_in[0];
    const int*   mask   = (const int*)  d_in[1];
    const float* qkv_w  = (const float*)d_in[2];
    const float* proj_w = (const float*)d_in[3];
    const float* proj_b = (const float*)d_in[4];
    float*       out    = (float*)d_out;

    cudaFuncSetAttribute(attn_mma,
                         cudaFuncAttributeMaxDynamicSharedMemorySize, ATTN_SMEM);
    cudaFuncSetAttribute(gemm_mma<1>,
                         cudaFuncAttributeMaxDynamicSharedMemorySize, GEMM_SMEM);
    cudaFuncSetAttribute(gemm_mma<2>,
                         cudaFuncAttributeMaxDynamicSharedMemorySize, GEMM_SMEM);

    // prepack inputs into device globals (templates select destination)
    prepack<0><<<(8192 * 192 + 255) / 256, 256>>>(x,      8192);
    prepack<1><<<(2304 * 192 + 255) / 256, 256>>>(qkv_w,  2304);
    prepack<2><<<(768  * 192 + 255) / 256, 256>>>(proj_w, 768);

    gemm_mma<1><<<dim3(2304 / 128, 8192 / 128), 256, GEMM_SMEM>>>(nullptr, nullptr, 2304);
    attn_mma<<<dim3(Nseq / 128, Bc * Hh), 256, ATTN_SMEM>>>(mask);
    gemm_mma<2><<<dim3(768 / 128, 8192 / 128), 256, GEMM_SMEM>>>(proj_b, out, 768);
}

// round 16
// speedup vs baseline: 1.5634x; 1.0031x over previous
// v16: GEMM 3-stage pipeline (1 sync/chunk, 96KB smem, 2 CTA/SM) + mask
// prepacked to bf16 bias (shift-unpack adds). All else = passing v15.
#include <cuda_runtime.h>
#include <cuda_bf16.h>
#include <cstdint>

#define Bc   4
#define Nseq 2048
#define Cdim 768
#define Hh   12
#define Dd   64

using u64 = unsigned long long;
using u32 = unsigned int;

#define QS_CONST 92.33248261972106f    // 64 * log2(e)
#define MC_CONST -1442695.040888963f   // -1e6 * log2(e)

__device__ __forceinline__ float ex2(float x) {
    float y; asm("ex2.approx.f32 %0,%1;" : "=f"(y) : "f"(x)); return y;
}
__device__ __forceinline__ u32 smem_u32(const void* p) {
    u32 a; asm("{ .reg .u64 t; cvta.to.shared.u64 t, %1; cvt.u32.u64 %0, t; }" : "=r"(a) : "l"(p));
    return a;
}
__device__ __forceinline__ void ldm4(u32& r0, u32& r1, u32& r2, u32& r3, u32 addr) {
    asm volatile("ldmatrix.sync.aligned.m8n8.x4.shared.b16 {%0,%1,%2,%3},[%4];"
        : "=r"(r0), "=r"(r1), "=r"(r2), "=r"(r3) : "r"(addr));
}
__device__ __forceinline__ void mma16816(float* c, const u32* a, u32 b0, u32 b1) {
    asm volatile("mma.sync.aligned.m16n8k16.row.col.f32.bf16.bf16.f32 "
        "{%0,%1,%2,%3},{%4,%5,%6,%7},{%8,%9},{%0,%1,%2,%3};"
        : "+f"(c[0]), "+f"(c[1]), "+f"(c[2]), "+f"(c[3])
        : "r"(a[0]), "r"(a[1]), "r"(a[2]), "r"(a[3]), "r"(b0), "r"(b1));
}
__device__ __forceinline__ u32 pkbf(float lo, float hi) {
    u32 r; asm("cvt.rn.bf16x2.f32 %0,%1,%2;" : "=r"(r) : "f"(hi), "f"(lo)); return r;
}
__device__ __forceinline__ void split2(float x, float y, u32& hi, u32& lo) {
    hi = pkbf(x, y);
    float hx = __int_as_float(hi << 16);
    float hy = __int_as_float(hi & 0xFFFF0000u);
    lo = pkbf(x - hx, y - hy);
}
__device__ __forceinline__ float exp2p(float x) {
    x = fmaxf(x, -126.0f);
    float t = x + 12582912.0f;
    int  k  = __float_as_int(t) - 0x4B400000;
    float xf = x - (t - 12582912.0f);
    float p = 0.0096180f;
    p = p * xf + 0.0555041f;
    p = p * xf + 0.2402265f;
    p = p * xf + 0.6931472f;
    p = p * xf + 1.0f;
    return p * __int_as_float((k + 127) << 23);
}
__device__ __forceinline__ void cpa16(u32 dst, const void* src) {
    asm volatile("cp.async.cg.shared.global [%0], [%1], 16;" :: "r"(dst), "l"(src) : "memory");
}
#define CP_COMMIT() asm volatile("cp.async.commit_group;" ::: "memory")
#define CP_WAIT(n)  asm volatile("cp.async.wait_group %0;" :: "n"(n) : "memory")

// ---------- scratch ----------
__device__ __nv_bfloat16 g_xpk[(size_t)8192 * 1536];
__device__ __nv_bfloat16 g_wqkvpk[(size_t)2304 * 1536];
__device__ __nv_bfloat16 g_wprojpk[(size_t)768 * 1536];
__device__ __nv_bfloat16 g_aopk[(size_t)8192 * 1536];
__device__ __nv_bfloat16 g_mb[(size_t)2048 * 2048];        // mask * MC as bf16
__device__ __nv_bfloat16 g_qhi[(size_t)48 * 2048 * 64];
__device__ __nv_bfloat16 g_qlo[(size_t)48 * 2048 * 64];
__device__ __nv_bfloat16 g_khi[(size_t)48 * 2048 * 64];
__device__ __nv_bfloat16 g_klo[(size_t)48 * 2048 * 64];
__device__ __nv_bfloat16 g_vthi[(size_t)48 * 64 * 2048];   // [bh][d][n]
__device__ __nv_bfloat16 g_vtlo[(size_t)48 * 64 * 2048];

// ===========================================================================
// prepack kernels
// ===========================================================================
template<int DST>
__global__ void prepack(const float* __restrict__ src, int nrows) {
    int idx = blockIdx.x * 256 + threadIdx.x;
    if (idx >= nrows * 192) return;
    __nv_bfloat16* dst = (DST == 0) ? g_xpk : (DST == 1) ? g_wqkvpk : g_wprojpk;
    int r = idx / 192, q = idx - r * 192;
    int col = q * 4;
    int chunk = col >> 5, pos = col & 31;
    float4 v = *(const float4*)(src + (size_t)r * 768 + col);
    u32 h01, l01, h23, l23;
    split2(v.x, v.y, h01, l01);
    split2(v.z, v.w, h23, l23);
    __nv_bfloat16* base = dst + (size_t)r * 1536 + chunk * 64 + pos;
    *(u32*)(base)      = h01; *(u32*)(base + 2)  = h23;
    *(u32*)(base + 32) = l01; *(u32*)(base + 34) = l23;
}

__global__ void prepack_mask(const int* __restrict__ mask) {
    int idx = blockIdx.x * 256 + threadIdx.x;      // per 4 ints
    if (idx >= (2048 * 2048) / 4) return;
    int4 m = ((const int4*)mask)[idx];
    u32 p0 = pkbf((float)m.x * MC_CONST, (float)m.y * MC_CONST);
    u32 p1 = pkbf((float)m.z * MC_CONST, (float)m.w * MC_CONST);
    *(uint2*)(g_mb + (size_t)idx * 4) = make_uint2(p0, p1);
}

// ===========================================================================
// GEMM NT on prepacked operands — 3-stage cp.async pipeline, 1 sync/chunk.
// 96KB smem -> 2 CTA/SM. Compute/epilogue identical to v15.
// ===========================================================================
#define MTILE_B 16384
#define STG_B32 32768
#define GEMM_SMEM (3 * STG_B32)

__device__ __forceinline__ void issue_g(u32 dst, const __nv_bfloat16* __restrict__ pk,
                                        int kc, int t) {
#pragma unroll
    for (int it = 0; it < 4; ++it) {
        int slot = t + it * 256;
        int row  = slot >> 3, gg = slot & 7;
        u32 off = (u32)(row * 128 + gg * 16);
        u32 sw  = off ^ ((off >> 3) & 0x70);
        cpa16(dst + sw, (const char*)pk + (size_t)row * 3072 + kc * 128 + gg * 16);
    }
}

template<int MODE>
__global__ void __launch_bounds__(256, 2) gemm_mma(const float* __restrict__ bias,
                                                   float* __restrict__ C, int Nn) {
    extern __shared__ __align__(1024) char smem[];
    const u32 sb   = smem_u32(smem);
    const int t    = threadIdx.x, lane = t & 31, wid = t >> 5;
    const int i0   = blockIdx.y * 128, j0 = blockIdx.x * 128;
    const __nv_bfloat16* __restrict__ Ar =
        ((MODE == 1) ? g_xpk : g_aopk) + (size_t)i0 * 1536;
    const __nv_bfloat16* __restrict__ Br =
        ((MODE == 1) ? g_wqkvpk : g_wprojpk) + (size_t)j0 * 1536;

    const int m0  = (wid >> 2) * 64;
    const int n0  = (wid & 3) * 32;
    const int lr  = lane & 15;
    const int chi = lane >> 4;
    const u32 xorv = (u32)((lane & 7) << 4);

    float acc[4][4][4];
#pragma unroll
    for (int i = 0; i < 4; i++)
#pragma unroll
        for (int j = 0; j < 4; j++)
#pragma unroll
            for (int k = 0; k < 4; k++) acc[i][j][k] = 0.f;

    issue_g(sb + 0,       Ar, 0, t);
    issue_g(sb + MTILE_B, Br, 0, t);
    CP_COMMIT();
    issue_g(sb + STG_B32,           Ar, 1, t);
    issue_g(sb + STG_B32 + MTILE_B, Br, 1, t);
    CP_COMMIT();

    int stg_idx = 0;
    for (int kc = 0; kc < 24; ++kc) {
        if (kc < 23) { CP_WAIT(1); } else { CP_WAIT(0); }
        __syncthreads();
        // refill stage (kc+2)%3 (consumed at kc-1; all warps past it)
        if (kc + 2 < 24) {
            int rs = stg_idx + 2; if (rs >= 3) rs -= 3;
            u32 rb = sb + (u32)(rs * STG_B32);
            issue_g(rb,           Ar, kc + 2, t);
            issue_g(rb + MTILE_B, Br, kc + 2, t);
            CP_COMMIT();
        }

        const u32 base = sb + (u32)(stg_idx * STG_B32);
#pragma unroll
        for (int s = 0; s < 2; ++s) {
            const u32 csel = (u32)((2 * s + chi) << 4);
            const u32 ct_h = csel ^ xorv;
            const u32 ct_l = (64u + csel) ^ xorv;
            u32 ah[4][4], al[4][4];
#pragma unroll
            for (int i = 0; i < 4; i++) {
                u32 ra = base + (u32)((m0 + i * 16 + lr) * 128);
                ldm4(ah[i][0], ah[i][1], ah[i][2], ah[i][3], ra + ct_h);
                ldm4(al[i][0], al[i][1], al[i][2], al[i][3], ra + ct_l);
            }
            u32 bh[8], bl[8];
#pragma unroll
            for (int j = 0; j < 2; j++) {
                u32 rb = base + MTILE_B + (u32)((n0 + j * 16 + lr) * 128);
                ldm4(bh[j * 4 + 0], bh[j * 4 + 1], bh[j * 4 + 2], bh[j * 4 + 3], rb + ct_h);
                ldm4(bl[j * 4 + 0], bl[j * 4 + 1], bl[j * 4 + 2], bl[j * 4 + 3], rb + ct_l);
            }
#pragma unroll
            for (int i = 0; i < 4; i++)
#pragma unroll
                for (int jj = 0; jj < 4; jj++) {
                    int j4 = (jj >> 1) * 4 + (jj & 1);
                    mma16816(acc[i][jj], ah[i], bh[j4], bh[j4 + 2]);
                    mma16816(acc[i][jj], ah[i], bl[j4], bl[j4 + 2]);
                    mma16816(acc[i][jj], al[i], bh[j4], bh[j4 + 2]);
                }
        }
        if (++stg_idx == 3) stg_idx = 0;
    }

#pragma unroll
    for (int i = 0; i < 4; i++) {
        int r0 = m0 + i * 16 + (lane >> 2);
#pragma unroll
        for (int jj = 0; jj < 4; jj++) {
            int col = n0 + jj * 8 + 2 * (lane & 3);
#pragma unroll
            for (int half = 0; half < 2; half++) {
                int gi = i0 + r0 + half * 8;
                int gj = j0 + col;
                float2 v;
                v.x = acc[i][jj][half * 2 + 0];
                v.y = acc[i][jj][half * 2 + 1];
                if (MODE == 1) {
                    int b = gi >> 11, n = gi & 2047;
                    int three = gj / 768, rem = gj - three * 768;
                    int hh = rem >> 6, d = rem & 63;
                    int bhI = b * 12 + hh;
                    if (three < 2) {
                        float sc = (three == 0) ? QS_CONST : 1.0f;
                        u32 hi, lo;
                        split2(v.x * sc, v.y * sc, hi, lo);
                        size_t idx = ((size_t)bhI * 2048 + n) * 64 + d;
                        __nv_bfloat16* ph = (three == 0) ? g_qhi : g_khi;
                        __nv_bfloat16* pl = (three == 0) ? g_qlo : g_klo;
                        *(u32*)(ph + idx) = hi;
                        *(u32*)(pl + idx) = lo;
                    } else {
                        size_t b0 = ((size_t)bhI * 64 + d) * 2048 + n;
                        __nv_bfloat16 hx = __float2bfloat16(v.x);
                        g_vthi[b0] = hx;
                        g_vtlo[b0] = __float2bfloat16(v.x - __bfloat162float(hx));
                        __nv_bfloat16 hy = __float2bfloat16(v.y);
                        g_vthi[b0 + 2048] = hy;
                        g_vtlo[b0 + 2048] = __float2bfloat16(v.y - __bfloat162float(hy));
                    }
                } else {
                    v.x += bias[gj];
                    v.y += bias[gj + 1];
                    *(float2*)(C + (size_t)gi * Nn + gj) = v;
                }
            }
        }
    }
}

// ===========================================================================
// HMMA flash attention — v13 structure; mask bias loaded as bf16 pairs.
// ===========================================================================
#define KB0   0
#define KB1   32768
#define VBUF  65536
#define ATTN_SMEM 98304

__device__ __forceinline__ void issue_k(u32 dst, int kbase, int t,
        const __nv_bfloat16* khi, const __nv_bfloat16* klo) {
#pragma unroll
    for (int it = 0; it < 4; ++it) {
        int slot = t + it * 256;
        int row  = slot >> 3, c = slot & 7;
        u32 dk = dst + (u32)(row * 128) + (u32)((c * 16) ^ ((row & 7) << 4));
        size_t so = (size_t)(kbase + row) * 64 + c * 8;
        cpa16(dk,          khi + so);
        cpa16(dk + 16384,  klo + so);
    }
}
__device__ __forceinline__ void issue_v(u32 dst, int kbase, int t,
        const __nv_bfloat16* vthi, const __nv_bfloat16* vtlo) {
#pragma unroll
    for (int it = 0; it < 4; ++it) {
        int slot = t + it * 256;
        int row  = slot >> 4, c = slot & 15;
        u32 dv = dst + (u32)(row * 256) + (u32)((c * 16) ^ ((row & 7) << 4));
        size_t so = (size_t)row * 2048 + kbase + c * 8;
        cpa16(dv,          vthi + so);
        cpa16(dv + 16384,  vtlo + so);
    }
}

__global__ void __launch_bounds__(256, 2) attn_mma() {
    extern __shared__ __align__(1024) char smem[];
    const u32 sb = smem_u32(smem);
    const int t  = threadIdx.x, lane = t & 31, w = t >> 5;
    const int g  = lane >> 2, tg = lane & 3;
    const int lr = lane & 15, chi = lane >> 4;
    const int bh = blockIdx.y;
    const int b  = bh / Hh, h = bh - b * Hh;
    const int qbase = blockIdx.x * 128;
    const int qw = w * 16;

    const __nv_bfloat16* qhi  = g_qhi  + (size_t)bh * 2048 * 64;
    const __nv_bfloat16* qlo  = g_qlo  + (size_t)bh * 2048 * 64;
    const __nv_bfloat16* khi  = g_khi  + (size_t)bh * 2048 * 64;
    const __nv_bfloat16* klo  = g_klo  + (size_t)bh * 2048 * 64;
    const __nv_bfloat16* vthi = g_vthi + (size_t)bh * 64 * 2048;
    const __nv_bfloat16* vtlo = g_vtlo + (size_t)bh * 64 * 2048;

#pragma unroll
    for (int it = 0; it < 4; ++it) {
        int slot = t + it * 256;
        int row  = slot >> 3, c = slot & 7;
        u32 dq = sb + VBUF + (u32)(row * 128) + (u32)((c * 16) ^ ((row & 7) << 4));
        size_t so = (size_t)(qbase + row) * 64 + c * 8;
        cpa16(dq,          qhi + so);
        cpa16(dq + 16384,  qlo + so);
    }
    CP_COMMIT();
    CP_WAIT(0);
    __syncthreads();

    u32 qh[4][4], ql[4][4];
    {
        int row = qw + lr;
        u32 xq = (u32)((row & 7) << 4);
#pragma unroll
        for (int ks = 0; ks < 4; ++ks) {
            u32 cb = (u32)((ks * 32 + chi * 16)) ^ xq;
            u32 ra = sb + VBUF + (u32)(row * 128) + cb;
            ldm4(qh[ks][0], qh[ks][1], qh[ks][2], qh[ks][3], ra);
            ldm4(ql[ks][0], ql[ks][1], ql[ks][2], ql[ks][3], ra + 16384);
        }
    }
    __syncthreads();

    issue_k(sb + KB0, 0, t, khi, klo);
    CP_COMMIT();
    issue_v(sb + VBUF, 0, t, vthi, vtlo);
    CP_COMMIT();
    issue_k(sb + KB1, 128, t, khi, klo);
    CP_COMMIT();

    float O[8][4];
#pragma unroll
    for (int i = 0; i < 8; i++)
#pragma unroll
        for (int j = 0; j < 4; j++) O[i][j] = 0.f;
    float mm0 = -1e30f, mm1 = -1e30f, ll0 = 0.f, ll1 = 0.f;

    const int mrow0 = (qbase + qw + g) * 2048;
    const int mrow1 = mrow0 + 8 * 2048;

    for (int kc = 0; kc < 16; ++kc) {
        const int kbase = kc * 128;
        const u32 kb = sb + (u32)((kc & 1) ? KB1 : KB0);
        if (kc < 15) { CP_WAIT(1); } else { CP_WAIT(0); }
        __syncthreads();

#pragma unroll
        for (int half = 0; half < 2; ++half) {
            const int koff = half * 64;
            float S[8][4];
#pragma unroll
            for (int i = 0; i < 8; i++)
#pragma unroll
                for (int j = 0; j < 4; j++) S[i][j] = 0.f;
#pragma unroll
            for (int jn = 0; jn < 4; ++jn) {
                int rowb = koff + jn * 16 + lr;
                u32 rba  = kb + (u32)(rowb * 128);
                u32 xorb = (u32)((rowb & 7) << 4);
#pragma unroll
                for (int ks = 0; ks < 4; ++ks) {
                    u32 off = ((u32)(ks * 32 + chi * 16)) ^ xorb;
                    u32 bh0, bh1, bh2, bh3, bl0, bl1, bl2, bl3;
                    ldm4(bh0, bh1, bh2, bh3, rba + off);
                    ldm4(bl0, bl1, bl2, bl3, rba + 16384 + off);
                    mma16816(S[2 * jn],     qh[ks], bh0, bh2);
                    mma16816(S[2 * jn + 1], qh[ks], bh1, bh3);
                    mma16816(S[2 * jn],     qh[ks], bl0, bl2);
                    mma16816(S[2 * jn + 1], qh[ks], bl1, bl3);
                    mma16816(S[2 * jn],     ql[ks], bh0, bh2);
                    mma16816(S[2 * jn + 1], ql[ks], bh1, bh3);
                }
            }

            float rmax0 = -1e30f, rmax1 = -1e30f;
#pragma unroll
            for (int nf = 0; nf < 8; ++nf) {
                int col = kbase + koff + nf * 8 + tg * 2;
                u32 mb0 = *(const u32*)(g_mb + mrow0 + col);
                u32 mb1 = *(const u32*)(g_mb + mrow1 + col);
                S[nf][0] += __int_as_float(mb0 << 16);
                S[nf][1] += __int_as_float(mb0 & 0xFFFF0000u);
                S[nf][2] += __int_as_float(mb1 << 16);
                S[nf][3] += __int_as_float(mb1 & 0xFFFF0000u);
                rmax0 = fmaxf(rmax0, fmaxf(S[nf][0], S[nf][1]));
                rmax1 = fmaxf(rmax1, fmaxf(S[nf][2], S[nf][3]));
            }
#pragma unroll
            for (int off = 1; off <= 2; off <<= 1) {
                rmax0 = fmaxf(rmax0, __shfl_xor_sync(0xffffffffu, rmax0, off));
                rmax1 = fmaxf(rmax1, __shfl_xor_sync(0xffffffffu, rmax1, off));
            }
            float mn0 = fmaxf(mm0, rmax0), mn1 = fmaxf(mm1, rmax1);
            float al0 = ex2(mm0 - mn0),    al1 = ex2(mm1 - mn1);
            mm0 = mn0; mm1 = mn1;
            float rs0 = 0.f, rs1 = 0.f;
#pragma unroll
            for (int nf = 0; nf < 8; ++nf) {
                S[nf][0] = exp2p(S[nf][0] - mn0);
                S[nf][1] = exp2p(S[nf][1] - mn0);
                S[nf][2] = exp2p(S[nf][2] - mn1);
                S[nf][3] = exp2p(S[nf][3] - mn1);
                rs0 += S[nf][0] + S[nf][1];
                rs1 += S[nf][2] + S[nf][3];
            }
#pragma unroll
            for (int off = 1; off <= 2; off <<= 1) {
                rs0 += __shfl_xor_sync(0xffffffffu, rs0, off);
                rs1 += __shfl_xor_sync(0xffffffffu, rs1, off);
            }
            ll0 = ll0 * al0 + rs0;
            ll1 = ll1 * al1 + rs1;
#pragma unroll
            for (int nf = 0; nf < 8; ++nf) {
                O[nf][0] *= al0; O[nf][1] *= al0;
                O[nf][2] *= al1; O[nf][3] *= al1;
            }

#pragma unroll
            for (int ks2 = 0; ks2 < 4; ++ks2) {
                u32 ahi[4], alo[4];
                split2(S[2 * ks2][0],     S[2 * ks2][1],     ahi[0], alo[0]);
                split2(S[2 * ks2][2],     S[2 * ks2][3],     ahi[1], alo[1]);
                split2(S[2 * ks2 + 1][0], S[2 * ks2 + 1][1], ahi[2], alo[2]);
                split2(S[2 * ks2 + 1][2], S[2 * ks2 + 1][3], ahi[3], alo[3]);
#pragma unroll
                for (int jd = 0; jd < 4; ++jd) {
                    int rowd = jd * 16 + lr;
                    u32 aoff = (u32)(rowd * 256) +
                               (((u32)(koff * 2 + ks2 * 32 + chi * 16)) ^ (u32)((rowd & 7) << 4));
                    u32 b0, b1, b2, b3;
                    ldm4(b0, b1, b2, b3, sb + VBUF + aoff);
                    mma16816(O[2 * jd],     ahi, b0, b2);
                    mma16816(O[2 * jd + 1], ahi, b1, b3);
                    mma16816(O[2 * jd],     alo, b0, b2);
                    mma16816(O[2 * jd + 1], alo, b1, b3);
                    u32 c0, c1, c2, c3;
                    ldm4(c0, c1, c2, c3, sb + VBUF + 16384 + aoff);
                    mma16816(O[2 * jd],     ahi, c0, c2);
                    mma16816(O[2 * jd + 1], ahi, c1, c3);
                }
            }
        }

        __syncthreads();
        if (kc + 1 < 16) {
            issue_v(sb + VBUF, (kc + 1) * 128, t, vthi, vtlo);
            CP_COMMIT();
        }
        if (kc + 2 < 16) {
            issue_k(kb, (kc + 2) * 128, t, khi, klo);
            CP_COMMIT();
        }
    }

    // ---- write O (normalized) to packed g_aopk for GEMM2 ----
    float inv0 = 1.f / ll0, inv1 = 1.f / ll1;
    int row0 = b * Nseq + qbase + qw + g;
    int row1 = row0 + 8;
#pragma unroll
    for (int nf = 0; nf < 8; ++nf) {
        int col   = h * 64 + nf * 8 + tg * 2;
        int chunk = col >> 5, pos = col & 31;
        u32 hi, lo;
        split2(O[nf][0] * inv0, O[nf][1] * inv0, hi, lo);
        __nv_bfloat16* p0 = g_aopk + (size_t)row0 * 1536 + chunk * 64 + pos;
        *(u32*)p0        = hi;
        *(u32*)(p0 + 32) = lo;
        split2(O[nf][2] * inv1, O[nf][3] * inv1, hi, lo);
        __nv_bfloat16* p1 = g_aopk + (size_t)row1 * 1536 + chunk * 64 + pos;
        *(u32*)p1        = hi;
        *(u32*)(p1 + 32) = lo;
    }
}

// ---------------------------------------------------------------------------
extern "C" void kernel_launch(void* const* d_in, const int* in_sizes, int n_in,
                              void* d_out, int out_size) {
    const float* x      = (const float*)d_in[0];
    const int*   mask   = (const int*)  d_in[1];
    const float* qkv_w  = (const float*)d_in[2];
    const float* proj_w = (const float*)d_in[3];
    const float* proj_b = (const float*)d_in[4];
    float*       out    = (float*)d_out;

    cudaFuncSetAttribute(attn_mma,
                         cudaFuncAttributeMaxDynamicSharedMemorySize, ATTN_SMEM);
    cudaFuncSetAttribute(gemm_mma<1>,
                         cudaFuncAttributeMaxDynamicSharedMemorySize, GEMM_SMEM);
    cudaFuncSetAttribute(gemm_mma<2>,
                         cudaFuncAttributeMaxDynamicSharedMemorySize, GEMM_SMEM);

    prepack<0><<<(8192 * 192 + 255) / 256, 256>>>(x,      8192);
    prepack<1><<<(2304 * 192 + 255) / 256, 256>>>(qkv_w,  2304);
    prepack<2><<<(768  * 192 + 255) / 256, 256>>>(proj_w, 768);
    prepack_mask<<<(2048 * 2048 / 4 + 255) / 256, 256>>>(mask);

    gemm_mma<1><<<dim3(2304 / 128, 8192 / 128), 256, GEMM_SMEM>>>(nullptr, nullptr, 2304);
    attn_mma<<<dim3(Nseq / 128, Bc * Hh), 256, ATTN_SMEM>>>();
    gemm_mma<2><<<dim3(768 / 128, 8192 / 128), 256, GEMM_SMEM>>>(proj_b, out, 768);
}